// round 2
// baseline (speedup 1.0000x reference)
#include <cuda_runtime.h>
#include <cstdint>

// Problem constants (fixed by setup_inputs)
#define B_   2
#define LQ_  4096
#define C_   384
#define M_   4
#define H_   6
#define P_   4
#define DH_  64
#define ROWS_ (B_ * LQ_)          // 8192
#define OFFN_ (H_ * P_ * 2)       // 48
#define AWN_  (H_ * P_)           // 24

// ---------------- scratch (static device globals; no allocation) -------------
__device__ float g_qn   [ROWS_ * C_];
__device__ float g_fn   [ROWS_ * C_];
__device__ float g_value[ROWS_ * C_];
__device__ float g_off  [ROWS_ * OFFN_];
__device__ float g_aw   [ROWS_ * AWN_];
__device__ float g_attn [ROWS_ * C_];

// ---------------- LayerNorm: one block per row ------------------------------
__global__ void ln_kernel(const float* __restrict__ x,
                          const float* __restrict__ g,
                          const float* __restrict__ b,
                          float* __restrict__ y)
{
    const int row = blockIdx.x;
    const float* xr = x + (size_t)row * C_;
    float sum = 0.f, sumsq = 0.f;
    for (int i = threadIdx.x; i < C_; i += blockDim.x) {
        float v = xr[i];
        sum += v; sumsq += v * v;
    }
    __shared__ float s1[32], s2[32];
    #pragma unroll
    for (int o = 16; o; o >>= 1) {
        sum   += __shfl_xor_sync(0xffffffffu, sum, o);
        sumsq += __shfl_xor_sync(0xffffffffu, sumsq, o);
    }
    int w = threadIdx.x >> 5, l = threadIdx.x & 31;
    if (l == 0) { s1[w] = sum; s2[w] = sumsq; }
    __syncthreads();
    if (w == 0) {
        int nw = blockDim.x >> 5;
        sum   = (l < nw) ? s1[l] : 0.f;
        sumsq = (l < nw) ? s2[l] : 0.f;
        #pragma unroll
        for (int o = 16; o; o >>= 1) {
            sum   += __shfl_xor_sync(0xffffffffu, sum, o);
            sumsq += __shfl_xor_sync(0xffffffffu, sumsq, o);
        }
        if (l == 0) { s1[0] = sum; s2[0] = sumsq; }
    }
    __syncthreads();
    const float mean = s1[0] * (1.f / C_);
    const float var  = s2[0] * (1.f / C_) - mean * mean;
    const float inv  = rsqrtf(var + 1e-6f);
    float* yr = y + (size_t)row * C_;
    for (int i = threadIdx.x; i < C_; i += blockDim.x)
        yr[i] = (xr[i] - mean) * inv * g[i] + b[i];
}

// ---------------- fp32 tiled GEMM with fused epilogue -----------------------
// C = A(MxK) * B(KxN) + bias;  if gamma: Cdst += gamma[n]*result; else Cdst = result.
#define TILE 64
#define KT   16
__global__ void gemm_kernel(const float* __restrict__ A,
                            const float* __restrict__ Bm,
                            const float* __restrict__ bias,
                            float* __restrict__ Cm,
                            int Mrows, int N, int K,
                            const float* __restrict__ gamma)
{
    __shared__ float As[KT][TILE + 1];
    __shared__ float Bs[KT][TILE + 1];
    const int tx = threadIdx.x & 15;       // 16x16 thread grid
    const int ty = threadIdx.x >> 4;
    const int row0 = blockIdx.y * TILE;
    const int col0 = blockIdx.x * TILE;

    float acc[4][4] = {};

    for (int k0 = 0; k0 < K; k0 += KT) {
        #pragma unroll
        for (int i = threadIdx.x; i < TILE * KT; i += 256) {
            int r = i >> 4, c = i & 15;
            As[c][r] = A[(size_t)(row0 + r) * K + (k0 + c)];
        }
        #pragma unroll
        for (int i = threadIdx.x; i < KT * TILE; i += 256) {
            int r = i >> 6, c = i & 63;
            int gc = col0 + c;
            Bs[r][c] = (gc < N) ? Bm[(size_t)(k0 + r) * N + gc] : 0.f;
        }
        __syncthreads();
        #pragma unroll
        for (int kk = 0; kk < KT; kk++) {
            float a[4], bb[4];
            #pragma unroll
            for (int i = 0; i < 4; i++) a[i]  = As[kk][ty * 4 + i];
            #pragma unroll
            for (int j = 0; j < 4; j++) bb[j] = Bs[kk][tx * 4 + j];
            #pragma unroll
            for (int i = 0; i < 4; i++)
                #pragma unroll
                for (int j = 0; j < 4; j++)
                    acc[i][j] = fmaf(a[i], bb[j], acc[i][j]);
        }
        __syncthreads();
    }

    #pragma unroll
    for (int i = 0; i < 4; i++) {
        int r = row0 + ty * 4 + i;
        #pragma unroll
        for (int j = 0; j < 4; j++) {
            int c = col0 + tx * 4 + j;
            if (c >= N) continue;
            float v = acc[i][j] + (bias ? bias[c] : 0.f);
            size_t o = (size_t)r * N + c;
            if (gamma) Cm[o] += gamma[c] * v;
            else       Cm[o] = v;
        }
    }
}

// ---------------- out = query (init residual) --------------------------------
__global__ void copy_kernel(const float* __restrict__ src, float* __restrict__ dst, int n)
{
    int i = blockIdx.x * blockDim.x + threadIdx.x;
    if (i < n) dst[i] = src[i];
}

// ---------------- deformable bilinear sampling + softmax(aw) -----------------
// shapes_raw / lstart_raw are viewed as int32 words. Robust to int32 OR int64
// storage: int64 [h,w] -> words [h,0,w,0]; int32 [h,w] -> words [h,w].
// Since h >= 1, words[1]==0 identifies int64.
__global__ void sample_kernel(const float* __restrict__ value,   // (B, Lq, H, Dh)
                              const float* __restrict__ ref,     // (B, Lq, 1, 2)
                              const float* __restrict__ off,     // (B*Lq, 48)
                              const float* __restrict__ aw,      // (B*Lq, 24)
                              float* __restrict__ attn,          // (B*Lq, C)
                              const int* __restrict__ shapes_raw,
                              const int* __restrict__ lstart_raw)
{
    const int idx = blockIdx.x * 4 + (threadIdx.x >> 6);   // over B*Lq*H
    const int d   = threadIdx.x & 63;
    if (idx >= ROWS_ * H_) return;
    const int h  = idx % H_;
    const int bq = idx / H_;
    const int b  = bq / LQ_;

    // dtype-robust decode of spatial shape [h, w] and level start
    const int gh = shapes_raw[0];
    const int w1 = shapes_raw[1];
    const int gw = (w1 != 0) ? w1 : shapes_raw[2];
    const int st = lstart_raw[0];   // 0 under either encoding (low word)

    // softmax over the 4 attention weights for this (bq, h)
    float a4[P_];
    float amax = -1e30f;
    #pragma unroll
    for (int p = 0; p < P_; p++) {
        a4[p] = aw[(size_t)bq * AWN_ + h * P_ + p];
        amax = fmaxf(amax, a4[p]);
    }
    float asum = 0.f;
    #pragma unroll
    for (int p = 0; p < P_; p++) { a4[p] = __expf(a4[p] - amax); asum += a4[p]; }
    const float ainv = 1.f / asum;

    const float rx = ref[(size_t)bq * 2 + 0];
    const float ry = ref[(size_t)bq * 2 + 1];

    const float inv_w = 1.f / (float)gw;
    const float inv_h = 1.f / (float)gh;

    float out = 0.f;
    #pragma unroll
    for (int p = 0; p < P_; p++) {
        const float ox = off[(size_t)bq * OFFN_ + h * (P_ * 2) + p * 2 + 0];
        const float oy = off[(size_t)bq * OFFN_ + h * (P_ * 2) + p * 2 + 1];
        const float lx = rx + ox * inv_w;
        const float ly = ry + oy * inv_h;
        const float x = lx * (float)gw - 0.5f;
        const float y = ly * (float)gh - 0.5f;
        const float xf = floorf(x);
        const float yf = floorf(y);
        const int x0 = (int)xf;
        const int y0 = (int)yf;
        const float wx = x - xf;
        const float wy = y - yf;

        float s = 0.f;
        #pragma unroll
        for (int cy = 0; cy < 2; cy++) {
            const int yi = y0 + cy;
            if (yi < 0 || yi >= gh) continue;
            const float wyc = cy ? wy : (1.f - wy);
            #pragma unroll
            for (int cx = 0; cx < 2; cx++) {
                const int xi = x0 + cx;
                if (xi < 0 || xi >= gw) continue;
                const float wxc = cx ? wx : (1.f - wx);
                const int pos = st + yi * gw + xi;
                const float v = value[(((size_t)b * LQ_ + pos) * H_ + h) * DH_ + d];
                s = fmaf(wyc * wxc, v, s);
            }
        }
        out = fmaf(a4[p] * ainv, s, out);
    }
    attn[(size_t)bq * C_ + h * DH_ + d] = out;
}

// ---------------- driver -----------------------------------------------------
extern "C" void kernel_launch(void* const* d_in, const int* in_sizes, int n_in,
                              void* d_out, int out_size)
{
    const float* query = (const float*)d_in[0];
    const float* ref   = (const float*)d_in[1];
    const float* feat  = (const float*)d_in[2];
    const float* feato = (const float*)d_in[3];
    const float* qn_g  = (const float*)d_in[4];
    const float* qn_b  = (const float*)d_in[5];
    const float* fn_g  = (const float*)d_in[6];
    const float* fn_b  = (const float*)d_in[7];
    const float* Wv    = (const float*)d_in[8];
    const float* bv    = (const float*)d_in[9];
    const float* Woff  = (const float*)d_in[10];
    const float* boff  = (const float*)d_in[11];
    const float* Waw   = (const float*)d_in[12];
    const float* baw   = (const float*)d_in[13];
    const float* Wout  = (const float*)d_in[14];
    const float* bout  = (const float*)d_in[15];
    const float* gamma = (const float*)d_in[16];
    const int* shapes  = (const int*)d_in[17];
    const int* lstart  = (const int*)d_in[18];
    float* out = (float*)d_out;

    float *qn, *fn, *value, *off, *aw, *attn;
    cudaGetSymbolAddress((void**)&qn,    g_qn);
    cudaGetSymbolAddress((void**)&fn,    g_fn);
    cudaGetSymbolAddress((void**)&value, g_value);
    cudaGetSymbolAddress((void**)&off,   g_off);
    cudaGetSymbolAddress((void**)&aw,    g_aw);
    cudaGetSymbolAddress((void**)&attn,  g_attn);

    const int nElem = ROWS_ * C_;

    // qn = LN(query)
    ln_kernel<<<ROWS_, 128>>>(query, qn_g, qn_b, qn);
    // out = query
    copy_kernel<<<(nElem + 255) / 256, 256>>>(query, out, nElem);

    dim3 gemmBlk(256);
    dim3 gridBig(C_ / TILE, ROWS_ / TILE);                 // 6 x 128
    dim3 gridOff((OFFN_ + TILE - 1) / TILE, ROWS_ / TILE); // 1 x 128
    dim3 gridAw((AWN_ + TILE - 1) / TILE, ROWS_ / TILE);   // 1 x 128

    for (int m = 0; m < M_; m++) {
        const float* feat_m = (m == 0) ? feat : (feato + (size_t)(m - 1) * ROWS_ * C_);

        // fn = LN(feat_m)
        ln_kernel<<<ROWS_, 128>>>(feat_m, fn_g + m * C_, fn_b + m * C_, fn);

        // value = fn @ Wv + bv
        gemm_kernel<<<gridBig, gemmBlk>>>(fn, Wv + (size_t)m * C_ * C_, bv + m * C_,
                                          value, ROWS_, C_, C_, nullptr);
        // off = qn @ Woff + boff
        gemm_kernel<<<gridOff, gemmBlk>>>(qn, Woff + (size_t)m * C_ * OFFN_, boff + m * OFFN_,
                                          off, ROWS_, OFFN_, C_, nullptr);
        // aw = qn @ Waw + baw
        gemm_kernel<<<gridAw, gemmBlk>>>(qn, Waw + (size_t)m * C_ * AWN_, baw + m * AWN_,
                                         aw, ROWS_, AWN_, C_, nullptr);

        // attn = deformable sampling
        sample_kernel<<<(ROWS_ * H_ + 3) / 4, 256>>>(value, ref, off, aw, attn, shapes, lstart);

        // out += gamma * (attn @ Wout + bout)
        gemm_kernel<<<gridBig, gemmBlk>>>(attn, Wout + (size_t)m * C_ * C_, bout + m * C_,
                                          out, ROWS_, C_, C_, gamma + m * C_);
    }
}

// round 3
// speedup vs baseline: 3.4618x; 3.4618x over previous
#include <cuda_runtime.h>
#include <cuda_bf16.h>
#include <cstdint>

// Problem constants (fixed by setup_inputs)
#define B_   2
#define LQ_  4096
#define C_   384
#define M_   4
#define H_   6
#define P_   4
#define DH_  64
#define ROWS_ (B_ * LQ_)          // 8192
#define OFFN_ (H_ * P_ * 2)       // 48
#define AWN_  (H_ * P_)           // 24
#define KDIM_ C_                  // 384
#define KITERS_ (KDIM_ / 32)      // 12

// ---------------- scratch (static device globals; no allocation) -------------
__device__ __nv_bfloat16 g_qn   [ROWS_ * C_];
__device__ __nv_bfloat16 g_fn   [ROWS_ * C_];
__device__ float         g_value[ROWS_ * C_];
__device__ float         g_off  [ROWS_ * OFFN_];
__device__ float         g_aw   [ROWS_ * AWN_];
__device__ __nv_bfloat16 g_attn [ROWS_ * C_];
__device__ __nv_bfloat16 g_Wv_b  [M_ * C_ * C_];
__device__ __nv_bfloat16 g_Woff_b[M_ * C_ * OFFN_];
__device__ __nv_bfloat16 g_Waw_b [M_ * C_ * AWN_];
__device__ __nv_bfloat16 g_Wout_b[M_ * C_ * C_];

// ---------------- fp32 -> bf16 convert ---------------------------------------
__global__ void f2b_kernel(const float* __restrict__ x, __nv_bfloat16* __restrict__ y, int n)
{
    int i = blockIdx.x * blockDim.x + threadIdx.x;
    if (i < n) y[i] = __float2bfloat16(x[i]);
}

// ---------------- LayerNorm: one block per row, bf16 output ------------------
__global__ void ln_kernel(const float* __restrict__ x,
                          const float* __restrict__ g,
                          const float* __restrict__ b,
                          __nv_bfloat16* __restrict__ y)
{
    const int row = blockIdx.x;
    const float* xr = x + (size_t)row * C_;
    float sum = 0.f, sumsq = 0.f;
    for (int i = threadIdx.x; i < C_; i += blockDim.x) {
        float v = xr[i];
        sum += v; sumsq += v * v;
    }
    __shared__ float s1[32], s2[32];
    #pragma unroll
    for (int o = 16; o; o >>= 1) {
        sum   += __shfl_xor_sync(0xffffffffu, sum, o);
        sumsq += __shfl_xor_sync(0xffffffffu, sumsq, o);
    }
    int w = threadIdx.x >> 5, l = threadIdx.x & 31;
    if (l == 0) { s1[w] = sum; s2[w] = sumsq; }
    __syncthreads();
    if (w == 0) {
        int nw = blockDim.x >> 5;
        sum   = (l < nw) ? s1[l] : 0.f;
        sumsq = (l < nw) ? s2[l] : 0.f;
        #pragma unroll
        for (int o = 16; o; o >>= 1) {
            sum   += __shfl_xor_sync(0xffffffffu, sum, o);
            sumsq += __shfl_xor_sync(0xffffffffu, sumsq, o);
        }
        if (l == 0) { s1[0] = sum; s2[0] = sumsq; }
    }
    __syncthreads();
    const float mean = s1[0] * (1.f / C_);
    const float var  = s2[0] * (1.f / C_) - mean * mean;
    const float inv  = rsqrtf(var + 1e-6f);
    __nv_bfloat16* yr = y + (size_t)row * C_;
    for (int i = threadIdx.x; i < C_; i += blockDim.x)
        yr[i] = __float2bfloat16((xr[i] - mean) * inv * g[i] + b[i]);
}

// ---------------- bf16 tensor-core GEMM --------------------------------------
// C(fp32) = A(bf16, ROWSxK) @ W(bf16, KxN row-major) + bias
// if gamma: Cm += gamma[n] * result; else Cm = result.
// CTA tile 128x64, 256 threads (8 warps, 4M x 2N), warp tile 32x32.
// K fixed = 384 (12 iters of KT=32), cp.async 2-stage pipeline.
#define AS_STRIDE 40
#define BS_STRIDE 72

__global__ __launch_bounds__(256) void gemm_bf16(const __nv_bfloat16* __restrict__ A,
                                                 const __nv_bfloat16* __restrict__ W,
                                                 const float* __restrict__ bias,
                                                 float* __restrict__ Cm, int N,
                                                 const float* __restrict__ gamma)
{
    __shared__ alignas(16) __nv_bfloat16 As[2][128][AS_STRIDE];
    __shared__ alignas(16) __nv_bfloat16 Bs[2][32][BS_STRIDE];

    const int tid = threadIdx.x;
    const int w = tid >> 5, l = tid & 31;
    const int warpM = (w & 3) << 5;     // 0,32,64,96
    const int warpN = (w >> 2) << 5;    // 0,32
    const int row0 = blockIdx.y * 128;
    const int col0 = blockIdx.x * 64;

    float acc[2][4][4];
    #pragma unroll
    for (int mi = 0; mi < 2; mi++)
        #pragma unroll
        for (int nj = 0; nj < 4; nj++)
            #pragma unroll
            for (int q = 0; q < 4; q++) acc[mi][nj][q] = 0.f;

    // per-thread load coordinates
    const int ar0 = tid >> 1;                  // pairs of A chunks: q = 2*tid..2*tid+1
    const int br  = tid >> 3, bch = tid & 7;   // B: row, 16B chunk

    for (int it = 0; it <= KITERS_; it++) {
        // issue loads for tile 'it' into stage it&1 (skip when past end)
        if (it < KITERS_) {
            const int st = it & 1;
            const int k0 = it * 32;
            #pragma unroll
            for (int i = 0; i < 2; i++) {
                int q = tid * 2 + i;
                int r = q >> 2, kc = q & 3;
                uint32_t d = (uint32_t)__cvta_generic_to_shared(&As[st][r][kc * 8]);
                const __nv_bfloat16* s = A + (size_t)(row0 + r) * KDIM_ + k0 + kc * 8;
                asm volatile("cp.async.ca.shared.global [%0], [%1], 16;\n" :: "r"(d), "l"(s));
            }
            {
                int c = bch * 8;
                uint32_t d = (uint32_t)__cvta_generic_to_shared(&Bs[st][br][c]);
                const __nv_bfloat16* s = W + (size_t)(k0 + br) * N + col0 + c;
                int sb = (col0 + c < N) ? 16 : 0;
                if (sb == 0) s = W;  // keep address in-bounds; 0 bytes read
                asm volatile("cp.async.ca.shared.global [%0], [%1], 16, %2;\n"
                             :: "r"(d), "l"(s), "r"(sb));
            }
            asm volatile("cp.async.commit_group;\n");
        }
        if (it == 0) continue;  // nothing to compute yet

        // wait for tile it-1 (and ensure visibility)
        if (it < KITERS_)
            asm volatile("cp.async.wait_group 1;\n");   // allow the just-issued group to fly
        else
            asm volatile("cp.async.wait_group 0;\n");
        __syncthreads();

        const int st = (it - 1) & 1;
        #pragma unroll
        for (int s = 0; s < 2; s++) {
            const int k16 = s * 16;
            uint32_t a[2][4], bfr[2][4];
            #pragma unroll
            for (int mi = 0; mi < 2; mi++) {
                uint32_t addr = (uint32_t)__cvta_generic_to_shared(
                    &As[st][warpM + mi * 16 + (l & 15)][k16 + (l >> 4) * 8]);
                asm volatile("ldmatrix.sync.aligned.m8n8.x4.shared.b16 {%0,%1,%2,%3}, [%4];\n"
                    : "=r"(a[mi][0]), "=r"(a[mi][1]), "=r"(a[mi][2]), "=r"(a[mi][3])
                    : "r"(addr));
            }
            #pragma unroll
            for (int np = 0; np < 2; np++) {
                uint32_t addr = (uint32_t)__cvta_generic_to_shared(
                    &Bs[st][k16 + (l & 15)][warpN + np * 16 + (l >> 4) * 8]);
                asm volatile("ldmatrix.sync.aligned.m8n8.x4.trans.shared.b16 {%0,%1,%2,%3}, [%4];\n"
                    : "=r"(bfr[np][0]), "=r"(bfr[np][1]), "=r"(bfr[np][2]), "=r"(bfr[np][3])
                    : "r"(addr));
            }
            #pragma unroll
            for (int mi = 0; mi < 2; mi++)
                #pragma unroll
                for (int nj = 0; nj < 4; nj++) {
                    uint32_t b0 = bfr[nj >> 1][(nj & 1) * 2];
                    uint32_t b1 = bfr[nj >> 1][(nj & 1) * 2 + 1];
                    asm volatile(
                        "mma.sync.aligned.m16n8k16.row.col.f32.bf16.bf16.f32 "
                        "{%0,%1,%2,%3}, {%4,%5,%6,%7}, {%8,%9}, {%0,%1,%2,%3};\n"
                        : "+f"(acc[mi][nj][0]), "+f"(acc[mi][nj][1]),
                          "+f"(acc[mi][nj][2]), "+f"(acc[mi][nj][3])
                        : "r"(a[mi][0]), "r"(a[mi][1]), "r"(a[mi][2]), "r"(a[mi][3]),
                          "r"(b0), "r"(b1));
                }
        }
        __syncthreads();
    }

    // epilogue: c0:(r,c) c1:(r,c+1) c2:(r+8,c) c3:(r+8,c+1)
    #pragma unroll
    for (int mi = 0; mi < 2; mi++) {
        const int r = row0 + warpM + mi * 16 + (l >> 2);
        #pragma unroll
        for (int nj = 0; nj < 4; nj++) {
            const int c = col0 + warpN + nj * 8 + ((l & 3) << 1);
            if (c >= N) continue;
            const float v0 = acc[mi][nj][0] + bias[c];
            const float v1 = acc[mi][nj][1] + bias[c + 1];
            const float v2 = acc[mi][nj][2] + bias[c];
            const float v3 = acc[mi][nj][3] + bias[c + 1];
            const size_t o0 = (size_t)r * N + c;
            const size_t o1 = (size_t)(r + 8) * N + c;
            if (gamma) {
                const float gc0 = gamma[c], gc1 = gamma[c + 1];
                Cm[o0]     += gc0 * v0;
                Cm[o0 + 1] += gc1 * v1;
                Cm[o1]     += gc0 * v2;
                Cm[o1 + 1] += gc1 * v3;
            } else {
                Cm[o0]     = v0;
                Cm[o0 + 1] = v1;
                Cm[o1]     = v2;
                Cm[o1 + 1] = v3;
            }
        }
    }
}

// ---------------- out = query (init residual) --------------------------------
__global__ void copy_kernel(const float* __restrict__ src, float* __restrict__ dst, int n)
{
    int i = blockIdx.x * blockDim.x + threadIdx.x;
    if (i < n) dst[i] = src[i];
}

// ---------------- deformable bilinear sampling + softmax(aw) -----------------
__global__ void sample_kernel(const float* __restrict__ value,   // (B, Lq, H, Dh)
                              const float* __restrict__ ref,     // (B, Lq, 1, 2)
                              const float* __restrict__ off,     // (B*Lq, 48)
                              const float* __restrict__ aw,      // (B*Lq, 24)
                              __nv_bfloat16* __restrict__ attn,  // (B*Lq, C) bf16
                              const int* __restrict__ shapes_raw,
                              const int* __restrict__ lstart_raw)
{
    const int idx = blockIdx.x * 4 + (threadIdx.x >> 6);   // over B*Lq*H
    const int d   = threadIdx.x & 63;
    if (idx >= ROWS_ * H_) return;
    const int h  = idx % H_;
    const int bq = idx / H_;
    const int b  = bq / LQ_;

    // dtype-robust decode (int32 or int64 storage)
    const int gh = shapes_raw[0];
    const int w1 = shapes_raw[1];
    const int gw = (w1 != 0) ? w1 : shapes_raw[2];
    const int st = lstart_raw[0];

    float a4[P_];
    float amax = -1e30f;
    #pragma unroll
    for (int p = 0; p < P_; p++) {
        a4[p] = aw[(size_t)bq * AWN_ + h * P_ + p];
        amax = fmaxf(amax, a4[p]);
    }
    float asum = 0.f;
    #pragma unroll
    for (int p = 0; p < P_; p++) { a4[p] = __expf(a4[p] - amax); asum += a4[p]; }
    const float ainv = 1.f / asum;

    const float rx = ref[(size_t)bq * 2 + 0];
    const float ry = ref[(size_t)bq * 2 + 1];
    const float inv_w = 1.f / (float)gw;
    const float inv_h = 1.f / (float)gh;

    float out = 0.f;
    #pragma unroll
    for (int p = 0; p < P_; p++) {
        const float ox = off[(size_t)bq * OFFN_ + h * (P_ * 2) + p * 2 + 0];
        const float oy = off[(size_t)bq * OFFN_ + h * (P_ * 2) + p * 2 + 1];
        const float x = (rx + ox * inv_w) * (float)gw - 0.5f;
        const float y = (ry + oy * inv_h) * (float)gh - 0.5f;
        const float xf = floorf(x);
        const float yf = floorf(y);
        const int x0 = (int)xf;
        const int y0 = (int)yf;
        const float wx = x - xf;
        const float wy = y - yf;

        float s = 0.f;
        #pragma unroll
        for (int cy = 0; cy < 2; cy++) {
            const int yi = y0 + cy;
            if (yi < 0 || yi >= gh) continue;
            const float wyc = cy ? wy : (1.f - wy);
            #pragma unroll
            for (int cx = 0; cx < 2; cx++) {
                const int xi = x0 + cx;
                if (xi < 0 || xi >= gw) continue;
                const float wxc = cx ? wx : (1.f - wx);
                const int pos = st + yi * gw + xi;
                const float v = value[(((size_t)b * LQ_ + pos) * H_ + h) * DH_ + d];
                s = fmaf(wyc * wxc, v, s);
            }
        }
        out = fmaf(a4[p] * ainv, s, out);
    }
    attn[(size_t)bq * C_ + h * DH_ + d] = __float2bfloat16(out);
}

// ---------------- driver -----------------------------------------------------
extern "C" void kernel_launch(void* const* d_in, const int* in_sizes, int n_in,
                              void* d_out, int out_size)
{
    const float* query = (const float*)d_in[0];
    const float* ref   = (const float*)d_in[1];
    const float* feat  = (const float*)d_in[2];
    const float* feato = (const float*)d_in[3];
    const float* qn_g  = (const float*)d_in[4];
    const float* qn_b  = (const float*)d_in[5];
    const float* fn_g  = (const float*)d_in[6];
    const float* fn_b  = (const float*)d_in[7];
    const float* Wv    = (const float*)d_in[8];
    const float* bv    = (const float*)d_in[9];
    const float* Woff  = (const float*)d_in[10];
    const float* boff  = (const float*)d_in[11];
    const float* Waw   = (const float*)d_in[12];
    const float* baw   = (const float*)d_in[13];
    const float* Wout  = (const float*)d_in[14];
    const float* bout  = (const float*)d_in[15];
    const float* gamma = (const float*)d_in[16];
    const int* shapes  = (const int*)d_in[17];
    const int* lstart  = (const int*)d_in[18];
    float* out = (float*)d_out;

    __nv_bfloat16 *qn, *fn, *attn, *Wv_b, *Woff_b, *Waw_b, *Wout_b;
    float *value, *off, *aw;
    cudaGetSymbolAddress((void**)&qn,    g_qn);
    cudaGetSymbolAddress((void**)&fn,    g_fn);
    cudaGetSymbolAddress((void**)&value, g_value);
    cudaGetSymbolAddress((void**)&off,   g_off);
    cudaGetSymbolAddress((void**)&aw,    g_aw);
    cudaGetSymbolAddress((void**)&attn,  g_attn);
    cudaGetSymbolAddress((void**)&Wv_b,  g_Wv_b);
    cudaGetSymbolAddress((void**)&Woff_b,g_Woff_b);
    cudaGetSymbolAddress((void**)&Waw_b, g_Waw_b);
    cudaGetSymbolAddress((void**)&Wout_b,g_Wout_b);

    const int nElem = ROWS_ * C_;

    // weight conversion fp32 -> bf16 (every call; cheap)
    f2b_kernel<<<(M_*C_*C_   + 255)/256, 256>>>(Wv,   Wv_b,   M_*C_*C_);
    f2b_kernel<<<(M_*C_*OFFN_+ 255)/256, 256>>>(Woff, Woff_b, M_*C_*OFFN_);
    f2b_kernel<<<(M_*C_*AWN_ + 255)/256, 256>>>(Waw,  Waw_b,  M_*C_*AWN_);
    f2b_kernel<<<(M_*C_*C_   + 255)/256, 256>>>(Wout, Wout_b, M_*C_*C_);

    // qn = LN(query) in bf16
    ln_kernel<<<ROWS_, 128>>>(query, qn_g, qn_b, qn);
    // out = query
    copy_kernel<<<(nElem + 255) / 256, 256>>>(query, out, nElem);

    dim3 blk(256);
    dim3 gridBig(C_ / 64, ROWS_ / 128);     // 6 x 64
    dim3 gridOff(1, ROWS_ / 128);           // N=48 -> 1 col tile
    dim3 gridAw(1, ROWS_ / 128);            // N=24 -> 1 col tile

    for (int m = 0; m < M_; m++) {
        const float* feat_m = (m == 0) ? feat : (feato + (size_t)(m - 1) * ROWS_ * C_);

        ln_kernel<<<ROWS_, 128>>>(feat_m, fn_g + m * C_, fn_b + m * C_, fn);

        gemm_bf16<<<gridBig, blk>>>(fn, Wv_b + (size_t)m * C_ * C_, bv + m * C_,
                                    value, C_, nullptr);
        gemm_bf16<<<gridOff, blk>>>(qn, Woff_b + (size_t)m * C_ * OFFN_, boff + m * OFFN_,
                                    off, OFFN_, nullptr);
        gemm_bf16<<<gridAw, blk>>>(qn, Waw_b + (size_t)m * C_ * AWN_, baw + m * AWN_,
                                   aw, AWN_, nullptr);

        sample_kernel<<<(ROWS_ * H_ + 3) / 4, 256>>>(value, ref, off, aw, attn, shapes, lstart);

        gemm_bf16<<<gridBig, blk>>>(attn, Wout_b + (size_t)m * C_ * C_, bout + m * C_,
                                    out, C_, gamma + m * C_);
    }
}

// round 4
// speedup vs baseline: 4.1613x; 1.2021x over previous
#include <cuda_runtime.h>
#include <cuda_bf16.h>
#include <cstdint>

// Problem constants (fixed by setup_inputs)
#define B_   2
#define LQ_  4096
#define C_   384
#define M_   4
#define H_   6
#define P_   4
#define DH_  64
#define ROWS_ (B_ * LQ_)          // 8192
#define OFFN_ 48                  // H*P*2
#define AWN_  24                  // H*P
#define FUSEN_ (M_ * (OFFN_ + AWN_))   // 288
#define KOUT_ (M_ * C_)                // 1536

// ---------------- scratch (static device globals; no allocation) -------------
__device__ __nv_bfloat16 g_qn    [ROWS_ * C_];
__device__ __nv_bfloat16 g_fn    [M_ * ROWS_ * C_];
__device__ __nv_bfloat16 g_value [M_ * ROWS_ * C_];
__device__ float         g_offaw [ROWS_ * FUSEN_];
__device__ __nv_bfloat16 g_attn  [ROWS_ * KOUT_];
__device__ __nv_bfloat16 g_Wv_b  [M_ * C_ * C_];
__device__ __nv_bfloat16 g_Wfo_b [C_ * FUSEN_];       // fused off+aw weights
__device__ float         g_bfo   [FUSEN_];            // fused off+aw bias
__device__ __nv_bfloat16 g_Wout_b[KOUT_ * C_];        // gamma-folded, K-stacked
__device__ float         g_bout  [C_];                // sum_m gamma*bout

// ---------------- weight pack kernels ----------------------------------------
__global__ void f2b_kernel(const float* __restrict__ x, __nv_bfloat16* __restrict__ y, int n)
{
    int i = blockIdx.x * blockDim.x + threadIdx.x;
    if (i < n) y[i] = __float2bfloat16(x[i]);
}

__global__ void pack_offaw_kernel(const float* __restrict__ Woff,  // [M][C][48]
                                  const float* __restrict__ Waw,   // [M][C][24]
                                  __nv_bfloat16* __restrict__ dst) // [C][288]
{
    int i = blockIdx.x * blockDim.x + threadIdx.x;
    if (i >= C_ * FUSEN_) return;
    int k = i / FUSEN_, j = i % FUSEN_;
    int m = j / 72, jj = j % 72;
    float v = (jj < OFFN_) ? Woff[((size_t)m * C_ + k) * OFFN_ + jj]
                           : Waw [((size_t)m * C_ + k) * AWN_  + (jj - OFFN_)];
    dst[i] = __float2bfloat16(v);
}

__global__ void pack_bias_kernel(const float* __restrict__ boff,   // [M][48]
                                 const float* __restrict__ baw,    // [M][24]
                                 const float* __restrict__ gamma,  // [M][C]
                                 const float* __restrict__ bout,   // [M][C]
                                 float* __restrict__ bfo,          // [288]
                                 float* __restrict__ bout_t)       // [384]
{
    int i = blockIdx.x * blockDim.x + threadIdx.x;
    if (i < FUSEN_) {
        int m = i / 72, jj = i % 72;
        bfo[i] = (jj < OFFN_) ? boff[m * OFFN_ + jj] : baw[m * AWN_ + jj - OFFN_];
    }
    if (i < C_) {
        float s = 0.f;
        #pragma unroll
        for (int m = 0; m < M_; m++) s += gamma[m * C_ + i] * bout[m * C_ + i];
        bout_t[i] = s;
    }
}

__global__ void pack_wout_kernel(const float* __restrict__ Wout,   // [M][C][C]
                                 const float* __restrict__ gamma,  // [M][C]
                                 __nv_bfloat16* __restrict__ dst)  // same index
{
    int i = blockIdx.x * blockDim.x + threadIdx.x;
    if (i >= M_ * C_ * C_) return;
    int m = i / (C_ * C_);
    int c = i % C_;
    dst[i] = __float2bfloat16(gamma[m * C_ + c] * Wout[i]);
}

// ---------------- fused LayerNorm: grid (ROWS, 5) ----------------------------
__global__ void ln_kernel(const float* __restrict__ query,
                          const float* __restrict__ feat,
                          const float* __restrict__ feato,
                          const float* __restrict__ qn_g, const float* __restrict__ qn_b,
                          const float* __restrict__ fn_g, const float* __restrict__ fn_b,
                          __nv_bfloat16* __restrict__ qn,
                          __nv_bfloat16* __restrict__ fnAll)
{
    const int row = blockIdx.x;
    const int src = blockIdx.y;   // 0=query, 1..4 = feats
    const float* xbase = (src == 0) ? query : (src == 1 ? feat
                         : feato + (size_t)(src - 2) * ROWS_ * C_);
    const float* g = (src == 0) ? qn_g : fn_g + (src - 1) * C_;
    const float* b = (src == 0) ? qn_b : fn_b + (src - 1) * C_;
    __nv_bfloat16* y = (src == 0) ? qn + (size_t)row * C_
                                  : fnAll + ((size_t)(src - 1) * ROWS_ + row) * C_;
    const float* xr = xbase + (size_t)row * C_;

    float sum = 0.f, sumsq = 0.f;
    for (int i = threadIdx.x; i < C_; i += blockDim.x) {
        float v = xr[i];
        sum += v; sumsq += v * v;
    }
    __shared__ float s1[32], s2[32];
    #pragma unroll
    for (int o = 16; o; o >>= 1) {
        sum   += __shfl_xor_sync(0xffffffffu, sum, o);
        sumsq += __shfl_xor_sync(0xffffffffu, sumsq, o);
    }
    int w = threadIdx.x >> 5, l = threadIdx.x & 31;
    if (l == 0) { s1[w] = sum; s2[w] = sumsq; }
    __syncthreads();
    if (w == 0) {
        int nw = blockDim.x >> 5;
        sum   = (l < nw) ? s1[l] : 0.f;
        sumsq = (l < nw) ? s2[l] : 0.f;
        #pragma unroll
        for (int o = 16; o; o >>= 1) {
            sum   += __shfl_xor_sync(0xffffffffu, sum, o);
            sumsq += __shfl_xor_sync(0xffffffffu, sumsq, o);
        }
        if (l == 0) { s1[0] = sum; s2[0] = sumsq; }
    }
    __syncthreads();
    const float mean = s1[0] * (1.f / C_);
    const float var  = s2[0] * (1.f / C_) - mean * mean;
    const float inv  = rsqrtf(var + 1e-6f);
    for (int i = threadIdx.x; i < C_; i += blockDim.x)
        y[i] = __float2bfloat16((xr[i] - mean) * inv * g[i] + b[i]);
}

// ---------------- bf16 tensor-core GEMM --------------------------------------
// template: KA = inner dim, MODE: 0 = fp32 store (offaw), 1 = bf16 store,
// z-batched over M_ (value), 2 = fp32 store with residual add (final).
#define AS_STRIDE 40
#define BS_STRIDE 72

template<int KA, int MODE>
__global__ __launch_bounds__(256) void gemm_bf16(const __nv_bfloat16* __restrict__ A,
                                                 const __nv_bfloat16* __restrict__ W,
                                                 const float* __restrict__ bias,
                                                 void* __restrict__ Cout, int N,
                                                 const float* __restrict__ residual)
{
    __shared__ alignas(16) __nv_bfloat16 As[2][128][AS_STRIDE];
    __shared__ alignas(16) __nv_bfloat16 Bs[2][32][BS_STRIDE];

    const int tid = threadIdx.x;
    const int w = tid >> 5, l = tid & 31;
    const int warpM = (w & 3) << 5;
    const int warpN = (w >> 2) << 5;
    const int row0 = blockIdx.y * 128;
    const int col0 = blockIdx.x * 64;

    if (MODE == 1) {
        const int zb = blockIdx.z;
        A    += (size_t)zb * ROWS_ * KA;
        W    += (size_t)zb * KA * N;
        bias += (size_t)zb * N;
    }

    float acc[2][4][4];
    #pragma unroll
    for (int mi = 0; mi < 2; mi++)
        #pragma unroll
        for (int nj = 0; nj < 4; nj++)
            #pragma unroll
            for (int q = 0; q < 4; q++) acc[mi][nj][q] = 0.f;

    const int br = tid >> 3, bch = tid & 7;
    const int KIT = KA / 32;

    for (int it = 0; it <= KIT; it++) {
        if (it < KIT) {
            const int st = it & 1;
            const int k0 = it * 32;
            #pragma unroll
            for (int i = 0; i < 2; i++) {
                int q = tid * 2 + i;
                int r = q >> 2, kc = q & 3;
                uint32_t d = (uint32_t)__cvta_generic_to_shared(&As[st][r][kc * 8]);
                const __nv_bfloat16* s = A + (size_t)(row0 + r) * KA + k0 + kc * 8;
                asm volatile("cp.async.ca.shared.global [%0], [%1], 16;\n" :: "r"(d), "l"(s));
            }
            {
                int c = bch * 8;
                uint32_t d = (uint32_t)__cvta_generic_to_shared(&Bs[st][br][c]);
                const __nv_bfloat16* s = W + (size_t)(k0 + br) * N + col0 + c;
                int sb = (col0 + c < N) ? 16 : 0;
                if (sb == 0) s = W;
                asm volatile("cp.async.ca.shared.global [%0], [%1], 16, %2;\n"
                             :: "r"(d), "l"(s), "r"(sb));
            }
            asm volatile("cp.async.commit_group;\n");
        }
        if (it == 0) continue;

        if (it < KIT) asm volatile("cp.async.wait_group 1;\n");
        else          asm volatile("cp.async.wait_group 0;\n");
        __syncthreads();

        const int st = (it - 1) & 1;
        #pragma unroll
        for (int s = 0; s < 2; s++) {
            const int k16 = s * 16;
            uint32_t a[2][4], bfr[2][4];
            #pragma unroll
            for (int mi = 0; mi < 2; mi++) {
                uint32_t addr = (uint32_t)__cvta_generic_to_shared(
                    &As[st][warpM + mi * 16 + (l & 15)][k16 + (l >> 4) * 8]);
                asm volatile("ldmatrix.sync.aligned.m8n8.x4.shared.b16 {%0,%1,%2,%3}, [%4];\n"
                    : "=r"(a[mi][0]), "=r"(a[mi][1]), "=r"(a[mi][2]), "=r"(a[mi][3])
                    : "r"(addr));
            }
            #pragma unroll
            for (int np = 0; np < 2; np++) {
                uint32_t addr = (uint32_t)__cvta_generic_to_shared(
                    &Bs[st][k16 + (l & 15)][warpN + np * 16 + (l >> 4) * 8]);
                asm volatile("ldmatrix.sync.aligned.m8n8.x4.trans.shared.b16 {%0,%1,%2,%3}, [%4];\n"
                    : "=r"(bfr[np][0]), "=r"(bfr[np][1]), "=r"(bfr[np][2]), "=r"(bfr[np][3])
                    : "r"(addr));
            }
            #pragma unroll
            for (int mi = 0; mi < 2; mi++)
                #pragma unroll
                for (int nj = 0; nj < 4; nj++) {
                    uint32_t b0 = bfr[nj >> 1][(nj & 1) * 2];
                    uint32_t b1 = bfr[nj >> 1][(nj & 1) * 2 + 1];
                    asm volatile(
                        "mma.sync.aligned.m16n8k16.row.col.f32.bf16.bf16.f32 "
                        "{%0,%1,%2,%3}, {%4,%5,%6,%7}, {%8,%9}, {%0,%1,%2,%3};\n"
                        : "+f"(acc[mi][nj][0]), "+f"(acc[mi][nj][1]),
                          "+f"(acc[mi][nj][2]), "+f"(acc[mi][nj][3])
                        : "r"(a[mi][0]), "r"(a[mi][1]), "r"(a[mi][2]), "r"(a[mi][3]),
                          "r"(b0), "r"(b1));
                }
        }
        __syncthreads();
    }

    // epilogue: accumulator frag -> (r,c),(r,c+1),(r+8,c),(r+8,c+1)
    #pragma unroll
    for (int mi = 0; mi < 2; mi++) {
        const int r = row0 + warpM + mi * 16 + (l >> 2);
        #pragma unroll
        for (int nj = 0; nj < 4; nj++) {
            const int c = col0 + warpN + nj * 8 + ((l & 3) << 1);
            if (c >= N) continue;
            const float b0 = bias[c], b1 = bias[c + 1];
            float v0 = acc[mi][nj][0] + b0;
            float v1 = acc[mi][nj][1] + b1;
            float v2 = acc[mi][nj][2] + b0;
            float v3 = acc[mi][nj][3] + b1;
            const size_t o0 = (size_t)r * N + c;
            const size_t o1 = (size_t)(r + 8) * N + c;
            if (MODE == 0) {
                float* Cm = (float*)Cout;
                *(float2*)&Cm[o0] = make_float2(v0, v1);
                *(float2*)&Cm[o1] = make_float2(v2, v3);
            } else if (MODE == 1) {
                __nv_bfloat16* Cm = (__nv_bfloat16*)Cout + (size_t)blockIdx.z * ROWS_ * N;
                *(__nv_bfloat162*)&Cm[o0] = __nv_bfloat162(__float2bfloat16(v0), __float2bfloat16(v1));
                *(__nv_bfloat162*)&Cm[o1] = __nv_bfloat162(__float2bfloat16(v2), __float2bfloat16(v3));
            } else {
                float* Cm = (float*)Cout;
                float2 r0 = *(const float2*)&residual[o0];
                float2 r1 = *(const float2*)&residual[o1];
                *(float2*)&Cm[o0] = make_float2(r0.x + v0, r0.y + v1);
                *(float2*)&Cm[o1] = make_float2(r1.x + v2, r1.y + v3);
            }
        }
    }
}

// ---------------- batched deformable sampling + softmax ----------------------
// one thread per (m, bq, h, d); value bf16, attn written K-concat [row][m*384+h*64+d]
__global__ void sample_kernel(const __nv_bfloat16* __restrict__ valueAll, // [M][B*Lq][C]
                              const float* __restrict__ ref,              // (B*Lq, 2)
                              const float* __restrict__ offaw,            // (B*Lq, 288)
                              __nv_bfloat16* __restrict__ attn,           // (B*Lq, 1536)
                              const int* __restrict__ shapes_raw,
                              const int* __restrict__ lstart_raw)
{
    const int idx = blockIdx.x * 4 + (threadIdx.x >> 6);   // over M*B*Lq*H
    const int d   = threadIdx.x & 63;
    if (idx >= M_ * ROWS_ * H_) return;
    const int m   = idx / (ROWS_ * H_);
    const int rem = idx % (ROWS_ * H_);
    const int h   = rem % H_;
    const int bq  = rem / H_;
    const int b   = bq / LQ_;

    const int gh = shapes_raw[0];
    const int w1 = shapes_raw[1];
    const int gw = (w1 != 0) ? w1 : shapes_raw[2];
    const int st = lstart_raw[0];

    const float* fo = offaw + (size_t)bq * FUSEN_ + m * 72;

    float a4[P_];
    float amax = -1e30f;
    #pragma unroll
    for (int p = 0; p < P_; p++) {
        a4[p] = fo[OFFN_ + h * P_ + p];
        amax = fmaxf(amax, a4[p]);
    }
    float asum = 0.f;
    #pragma unroll
    for (int p = 0; p < P_; p++) { a4[p] = __expf(a4[p] - amax); asum += a4[p]; }
    const float ainv = 1.f / asum;

    const float rx = ref[(size_t)bq * 2 + 0];
    const float ry = ref[(size_t)bq * 2 + 1];
    const float inv_w = 1.f / (float)gw;
    const float inv_h = 1.f / (float)gh;

    const __nv_bfloat16* value = valueAll + (size_t)m * ROWS_ * C_;

    float out = 0.f;
    #pragma unroll
    for (int p = 0; p < P_; p++) {
        const float ox = fo[h * (P_ * 2) + p * 2 + 0];
        const float oy = fo[h * (P_ * 2) + p * 2 + 1];
        const float x = (rx + ox * inv_w) * (float)gw - 0.5f;
        const float y = (ry + oy * inv_h) * (float)gh - 0.5f;
        const float xf = floorf(x);
        const float yf = floorf(y);
        const int x0 = (int)xf;
        const int y0 = (int)yf;
        const float wx = x - xf;
        const float wy = y - yf;

        float s = 0.f;
        #pragma unroll
        for (int cy = 0; cy < 2; cy++) {
            const int yi = y0 + cy;
            if (yi < 0 || yi >= gh) continue;
            const float wyc = cy ? wy : (1.f - wy);
            #pragma unroll
            for (int cx = 0; cx < 2; cx++) {
                const int xi = x0 + cx;
                if (xi < 0 || xi >= gw) continue;
                const float wxc = cx ? wx : (1.f - wx);
                const int pos = st + yi * gw + xi;
                const float v = __bfloat162float(
                    value[(((size_t)b * LQ_ + pos) * H_ + h) * DH_ + d]);
                s = fmaf(wyc * wxc, v, s);
            }
        }
        out = fmaf(a4[p] * ainv, s, out);
    }
    attn[(size_t)bq * KOUT_ + m * C_ + h * DH_ + d] = __float2bfloat16(out);
}

// ---------------- driver -----------------------------------------------------
extern "C" void kernel_launch(void* const* d_in, const int* in_sizes, int n_in,
                              void* d_out, int out_size)
{
    const float* query = (const float*)d_in[0];
    const float* ref   = (const float*)d_in[1];
    const float* feat  = (const float*)d_in[2];
    const float* feato = (const float*)d_in[3];
    const float* qn_g  = (const float*)d_in[4];
    const float* qn_b  = (const float*)d_in[5];
    const float* fn_g  = (const float*)d_in[6];
    const float* fn_b  = (const float*)d_in[7];
    const float* Wv    = (const float*)d_in[8];
    const float* bv    = (const float*)d_in[9];
    const float* Woff  = (const float*)d_in[10];
    const float* boff  = (const float*)d_in[11];
    const float* Waw   = (const float*)d_in[12];
    const float* baw   = (const float*)d_in[13];
    const float* Wout  = (const float*)d_in[14];
    const float* bout  = (const float*)d_in[15];
    const float* gamma = (const float*)d_in[16];
    const int* shapes  = (const int*)d_in[17];
    const int* lstart  = (const int*)d_in[18];
    float* out = (float*)d_out;

    __nv_bfloat16 *qn, *fn, *value, *attn, *Wv_b, *Wfo_b, *Wout_b;
    float *offaw, *bfo, *bout_t;
    cudaGetSymbolAddress((void**)&qn,     g_qn);
    cudaGetSymbolAddress((void**)&fn,     g_fn);
    cudaGetSymbolAddress((void**)&value,  g_value);
    cudaGetSymbolAddress((void**)&offaw,  g_offaw);
    cudaGetSymbolAddress((void**)&attn,   g_attn);
    cudaGetSymbolAddress((void**)&Wv_b,   g_Wv_b);
    cudaGetSymbolAddress((void**)&Wfo_b,  g_Wfo_b);
    cudaGetSymbolAddress((void**)&bfo,    g_bfo);
    cudaGetSymbolAddress((void**)&Wout_b, g_Wout_b);
    cudaGetSymbolAddress((void**)&bout_t, g_bout);

    // weight packing (every call; cheap, ~3 MB total)
    f2b_kernel<<<(M_*C_*C_ + 255)/256, 256>>>(Wv, Wv_b, M_*C_*C_);
    pack_offaw_kernel<<<(C_*FUSEN_ + 255)/256, 256>>>(Woff, Waw, Wfo_b);
    pack_bias_kernel<<<2, 256>>>(boff, baw, gamma, bout, bfo, bout_t);
    pack_wout_kernel<<<(M_*C_*C_ + 255)/256, 256>>>(Wout, gamma, Wout_b);

    // fused LN: qn + 4 fn
    ln_kernel<<<dim3(ROWS_, 5), 128>>>(query, feat, feato, qn_g, qn_b, fn_g, fn_b, qn, fn);

    // one GEMM for all off+aw (N=288)
    gemm_bf16<C_, 0><<<dim3((FUSEN_ + 63)/64, ROWS_/128), 256>>>(
        qn, Wfo_b, bfo, offaw, FUSEN_, nullptr);

    // batched value GEMMs (z = modality), bf16 output
    gemm_bf16<C_, 1><<<dim3(C_/64, ROWS_/128, M_), 256>>>(
        fn, Wv_b, bv, value, C_, nullptr);

    // batched deformable sampling (all modalities)
    sample_kernel<<<(M_ * ROWS_ * H_)/4, 256>>>(value, ref, offaw, attn, shapes, lstart);

    // final fused GEMM: out = query + attnAll @ Wout' + bout'
    gemm_bf16<KOUT_, 2><<<dim3(C_/64, ROWS_/128), 256>>>(
        attn, Wout_b, bout_t, out, C_, query);
}

// round 5
// speedup vs baseline: 6.8218x; 1.6393x over previous
#include <cuda_runtime.h>
#include <cuda_bf16.h>
#include <cstdint>

#define B_   2
#define LQ_  4096
#define C_   384
#define M_   4
#define H_   6
#define P_   4
#define DH_  64
#define ROWS_ (B_ * LQ_)          // 8192
#define OFFN_ 48
#define AWN_  24
#define FUSEN_ (M_ * (OFFN_ + AWN_))   // 288
#define KOUT_ (M_ * C_)                // 1536

// ---------------- scratch ----------------------------------------------------
__device__ __nv_bfloat16 g_qn    [ROWS_ * C_];
__device__ __nv_bfloat16 g_fn    [M_ * ROWS_ * C_];
__device__ __nv_bfloat16 g_value [M_ * ROWS_ * C_];
__device__ float         g_offaw [ROWS_ * FUSEN_];
__device__ __nv_bfloat16 g_attn  [ROWS_ * KOUT_];
__device__ __nv_bfloat16 g_Wv_b  [M_ * C_ * C_];
__device__ __nv_bfloat16 g_Wfo_b [C_ * FUSEN_];
__device__ float         g_bfo   [FUSEN_];
__device__ __nv_bfloat16 g_Wout_b[KOUT_ * C_];
__device__ float         g_bout  [C_];

// ---------------- fused weight packing (single launch) -----------------------
#define S1_ (M_ * C_ * C_)        // Wv -> bf16
#define S2_ (C_ * FUSEN_)         // offaw pack
#define S3_ (M_ * C_ * C_)        // Wout * gamma
__global__ void pack_all_kernel(const float* __restrict__ Wv,
                                const float* __restrict__ Woff,
                                const float* __restrict__ Waw,
                                const float* __restrict__ Wout,
                                const float* __restrict__ gamma,
                                const float* __restrict__ boff,
                                const float* __restrict__ baw,
                                const float* __restrict__ bout,
                                __nv_bfloat16* __restrict__ Wv_b,
                                __nv_bfloat16* __restrict__ Wfo_b,
                                __nv_bfloat16* __restrict__ Wout_b,
                                float* __restrict__ bfo,
                                float* __restrict__ bout_t)
{
    int i = blockIdx.x * blockDim.x + threadIdx.x;
    if (i < S1_) {
        Wv_b[i] = __float2bfloat16(Wv[i]);
    } else if (i < S1_ + S2_) {
        int j = i - S1_;
        int k = j / FUSEN_, jj = j % FUSEN_;
        int m = jj / 72, r = jj % 72;
        float v = (r < OFFN_) ? Woff[((size_t)m * C_ + k) * OFFN_ + r]
                              : Waw [((size_t)m * C_ + k) * AWN_  + (r - OFFN_)];
        Wfo_b[j] = __float2bfloat16(v);
    } else if (i < S1_ + S2_ + S3_) {
        int j = i - S1_ - S2_;
        int m = j / (C_ * C_);
        int c = j % C_;
        Wout_b[j] = __float2bfloat16(gamma[m * C_ + c] * Wout[j]);
    } else {
        int j = i - S1_ - S2_ - S3_;
        if (j < FUSEN_) {
            int m = j / 72, r = j % 72;
            bfo[j] = (r < OFFN_) ? boff[m * OFFN_ + r] : baw[m * AWN_ + r - OFFN_];
        } else if (j < FUSEN_ + C_) {
            int c = j - FUSEN_;
            float s = 0.f;
            #pragma unroll
            for (int m = 0; m < M_; m++) s += gamma[m * C_ + c] * bout[m * C_ + c];
            bout_t[c] = s;
        }
    }
}
#define PACK_TOTAL_ (S1_ + S2_ + S3_ + FUSEN_ + C_)

// ---------------- warp-per-row LayerNorm (5 sources fused) -------------------
__global__ void ln_kernel(const float* __restrict__ query,
                          const float* __restrict__ feat,
                          const float* __restrict__ feato,
                          const float* __restrict__ qn_g, const float* __restrict__ qn_b,
                          const float* __restrict__ fn_g, const float* __restrict__ fn_b,
                          __nv_bfloat16* __restrict__ qn,
                          __nv_bfloat16* __restrict__ fnAll)
{
    const int grow = blockIdx.x * 8 + (threadIdx.x >> 5);  // over 5*ROWS_
    const int l = threadIdx.x & 31;
    const int src = grow / ROWS_;
    const int row = grow - src * ROWS_;

    const float* xbase = (src == 0) ? query : (src == 1 ? feat
                         : feato + (size_t)(src - 2) * ROWS_ * C_);
    const float* g = (src == 0) ? qn_g : fn_g + (src - 1) * C_;
    const float* b = (src == 0) ? qn_b : fn_b + (src - 1) * C_;
    __nv_bfloat16* y = (src == 0) ? qn + (size_t)row * C_
                                  : fnAll + ((size_t)(src - 1) * ROWS_ + row) * C_;
    const float4* xr = (const float4*)(xbase + (size_t)row * C_);

    float4 v[3];
    float sum = 0.f, sumsq = 0.f;
    #pragma unroll
    for (int k = 0; k < 3; k++) {
        v[k] = xr[l + 32 * k];
        sum   += v[k].x + v[k].y + v[k].z + v[k].w;
        sumsq += v[k].x * v[k].x + v[k].y * v[k].y + v[k].z * v[k].z + v[k].w * v[k].w;
    }
    #pragma unroll
    for (int o = 16; o; o >>= 1) {
        sum   += __shfl_xor_sync(0xffffffffu, sum, o);
        sumsq += __shfl_xor_sync(0xffffffffu, sumsq, o);
    }
    const float mean = sum * (1.f / C_);
    const float var  = sumsq * (1.f / C_) - mean * mean;
    const float inv  = rsqrtf(var + 1e-6f);

    const float4* g4 = (const float4*)g;
    const float4* b4 = (const float4*)b;
    #pragma unroll
    for (int k = 0; k < 3; k++) {
        float4 gg = g4[l + 32 * k];
        float4 bb = b4[l + 32 * k];
        __nv_bfloat16 o0 = __float2bfloat16((v[k].x - mean) * inv * gg.x + bb.x);
        __nv_bfloat16 o1 = __float2bfloat16((v[k].y - mean) * inv * gg.y + bb.y);
        __nv_bfloat16 o2 = __float2bfloat16((v[k].z - mean) * inv * gg.z + bb.z);
        __nv_bfloat16 o3 = __float2bfloat16((v[k].w - mean) * inv * gg.w + bb.w);
        uint2 pk;
        pk.x = ((uint32_t)__bfloat16_as_ushort(o1) << 16) | __bfloat16_as_ushort(o0);
        pk.y = ((uint32_t)__bfloat16_as_ushort(o3) << 16) | __bfloat16_as_ushort(o2);
        *(uint2*)&y[(l + 32 * k) * 4] = pk;
    }
}

// ---------------- 64-wide GEMM (offaw only, N=288, fp32 out) -----------------
#define AS_STRIDE 40
#define BS_STRIDE 72
__global__ __launch_bounds__(256) void gemm64(const __nv_bfloat16* __restrict__ A,
                                              const __nv_bfloat16* __restrict__ W,
                                              const float* __restrict__ bias,
                                              float* __restrict__ Cm, int N)
{
    __shared__ alignas(16) __nv_bfloat16 As[2][128][AS_STRIDE];
    __shared__ alignas(16) __nv_bfloat16 Bs[2][32][BS_STRIDE];
    const int tid = threadIdx.x;
    const int w = tid >> 5, l = tid & 31;
    const int warpM = (w & 3) << 5;
    const int warpN = (w >> 2) << 5;
    const int row0 = blockIdx.y * 128;
    const int col0 = blockIdx.x * 64;

    float acc[2][4][4];
    #pragma unroll
    for (int mi = 0; mi < 2; mi++)
        #pragma unroll
        for (int nj = 0; nj < 4; nj++)
            #pragma unroll
            for (int q = 0; q < 4; q++) acc[mi][nj][q] = 0.f;

    const int br = tid >> 3, bch = tid & 7;
    const int KIT = C_ / 32;

    for (int it = 0; it <= KIT; it++) {
        if (it < KIT) {
            const int st = it & 1;
            const int k0 = it * 32;
            #pragma unroll
            for (int i = 0; i < 2; i++) {
                int q = tid * 2 + i;
                int r = q >> 2, kc = q & 3;
                uint32_t d = (uint32_t)__cvta_generic_to_shared(&As[st][r][kc * 8]);
                const __nv_bfloat16* s = A + (size_t)(row0 + r) * C_ + k0 + kc * 8;
                asm volatile("cp.async.ca.shared.global [%0], [%1], 16;\n" :: "r"(d), "l"(s));
            }
            {
                int c = bch * 8;
                uint32_t d = (uint32_t)__cvta_generic_to_shared(&Bs[st][br][c]);
                const __nv_bfloat16* s = W + (size_t)(k0 + br) * N + col0 + c;
                int sb = (col0 + c < N) ? 16 : 0;
                if (sb == 0) s = W;
                asm volatile("cp.async.ca.shared.global [%0], [%1], 16, %2;\n"
                             :: "r"(d), "l"(s), "r"(sb));
            }
            asm volatile("cp.async.commit_group;\n");
        }
        if (it == 0) continue;
        if (it < KIT) asm volatile("cp.async.wait_group 1;\n");
        else          asm volatile("cp.async.wait_group 0;\n");
        __syncthreads();

        const int st = (it - 1) & 1;
        #pragma unroll
        for (int s = 0; s < 2; s++) {
            const int k16 = s * 16;
            uint32_t a[2][4], bfr[2][4];
            #pragma unroll
            for (int mi = 0; mi < 2; mi++) {
                uint32_t addr = (uint32_t)__cvta_generic_to_shared(
                    &As[st][warpM + mi * 16 + (l & 15)][k16 + (l >> 4) * 8]);
                asm volatile("ldmatrix.sync.aligned.m8n8.x4.shared.b16 {%0,%1,%2,%3}, [%4];\n"
                    : "=r"(a[mi][0]), "=r"(a[mi][1]), "=r"(a[mi][2]), "=r"(a[mi][3]) : "r"(addr));
            }
            #pragma unroll
            for (int np = 0; np < 2; np++) {
                uint32_t addr = (uint32_t)__cvta_generic_to_shared(
                    &Bs[st][k16 + (l & 15)][warpN + np * 16 + (l >> 4) * 8]);
                asm volatile("ldmatrix.sync.aligned.m8n8.x4.trans.shared.b16 {%0,%1,%2,%3}, [%4];\n"
                    : "=r"(bfr[np][0]), "=r"(bfr[np][1]), "=r"(bfr[np][2]), "=r"(bfr[np][3]) : "r"(addr));
            }
            #pragma unroll
            for (int mi = 0; mi < 2; mi++)
                #pragma unroll
                for (int nj = 0; nj < 4; nj++) {
                    uint32_t b0 = bfr[nj >> 1][(nj & 1) * 2];
                    uint32_t b1 = bfr[nj >> 1][(nj & 1) * 2 + 1];
                    asm volatile(
                        "mma.sync.aligned.m16n8k16.row.col.f32.bf16.bf16.f32 "
                        "{%0,%1,%2,%3}, {%4,%5,%6,%7}, {%8,%9}, {%0,%1,%2,%3};\n"
                        : "+f"(acc[mi][nj][0]), "+f"(acc[mi][nj][1]),
                          "+f"(acc[mi][nj][2]), "+f"(acc[mi][nj][3])
                        : "r"(a[mi][0]), "r"(a[mi][1]), "r"(a[mi][2]), "r"(a[mi][3]),
                          "r"(b0), "r"(b1));
                }
        }
        __syncthreads();
    }

    #pragma unroll
    for (int mi = 0; mi < 2; mi++) {
        const int r = row0 + warpM + mi * 16 + (l >> 2);
        #pragma unroll
        for (int nj = 0; nj < 4; nj++) {
            const int c = col0 + warpN + nj * 8 + ((l & 3) << 1);
            if (c >= N) continue;
            const float b0 = bias[c], b1 = bias[c + 1];
            *(float2*)&Cm[(size_t)r * N + c]       = make_float2(acc[mi][nj][0] + b0, acc[mi][nj][1] + b1);
            *(float2*)&Cm[(size_t)(r + 8) * N + c] = make_float2(acc[mi][nj][2] + b0, acc[mi][nj][3] + b1);
        }
    }
}

// ---------------- 128x128 GEMM, N=384 exact ----------------------------------
// MODE 1: bf16 store, z-batched over modality. MODE 2: fp32 store + residual.
#define BS2_STRIDE 136
template<int KA, int MODE>
__global__ __launch_bounds__(256) void gemm128(const __nv_bfloat16* __restrict__ A,
                                               const __nv_bfloat16* __restrict__ W,
                                               const float* __restrict__ bias,
                                               void* __restrict__ Cout,
                                               const float* __restrict__ residual)
{
    __shared__ alignas(16) __nv_bfloat16 As[2][128][AS_STRIDE];
    __shared__ alignas(16) __nv_bfloat16 Bs[2][32][BS2_STRIDE];
    const int N = C_;
    const int tid = threadIdx.x;
    const int w = tid >> 5, l = tid & 31;
    const int warpM = (w & 1) << 6;     // 0,64
    const int warpN = (w >> 1) << 5;    // 0,32,64,96
    const int row0 = blockIdx.y * 128;
    const int col0 = blockIdx.x * 128;

    if (MODE == 1) {
        const int zb = blockIdx.z;
        A    += (size_t)zb * ROWS_ * KA;
        W    += (size_t)zb * KA * N;
        bias += (size_t)zb * N;
    }

    float acc[4][4][4];
    #pragma unroll
    for (int mi = 0; mi < 4; mi++)
        #pragma unroll
        for (int nj = 0; nj < 4; nj++)
            #pragma unroll
            for (int q = 0; q < 4; q++) acc[mi][nj][q] = 0.f;

    const int KIT = KA / 32;

    for (int it = 0; it <= KIT; it++) {
        if (it < KIT) {
            const int st = it & 1;
            const int k0 = it * 32;
            #pragma unroll
            for (int i = 0; i < 2; i++) {
                int q = tid * 2 + i;
                int r = q >> 2, kc = q & 3;
                uint32_t d = (uint32_t)__cvta_generic_to_shared(&As[st][r][kc * 8]);
                const __nv_bfloat16* s = A + (size_t)(row0 + r) * KA + k0 + kc * 8;
                asm volatile("cp.async.ca.shared.global [%0], [%1], 16;\n" :: "r"(d), "l"(s));
            }
            #pragma unroll
            for (int i = 0; i < 2; i++) {
                int r = (tid >> 4) + i * 16;
                int c = (tid & 15) * 8;
                uint32_t d = (uint32_t)__cvta_generic_to_shared(&Bs[st][r][c]);
                const __nv_bfloat16* s = W + (size_t)(k0 + r) * N + col0 + c;
                asm volatile("cp.async.ca.shared.global [%0], [%1], 16;\n" :: "r"(d), "l"(s));
            }
            asm volatile("cp.async.commit_group;\n");
        }
        if (it == 0) continue;
        if (it < KIT) asm volatile("cp.async.wait_group 1;\n");
        else          asm volatile("cp.async.wait_group 0;\n");
        __syncthreads();

        const int st = (it - 1) & 1;
        #pragma unroll
        for (int s = 0; s < 2; s++) {
            const int k16 = s * 16;
            uint32_t a[4][4], bfr[2][4];
            #pragma unroll
            for (int mi = 0; mi < 4; mi++) {
                uint32_t addr = (uint32_t)__cvta_generic_to_shared(
                    &As[st][warpM + mi * 16 + (l & 15)][k16 + (l >> 4) * 8]);
                asm volatile("ldmatrix.sync.aligned.m8n8.x4.shared.b16 {%0,%1,%2,%3}, [%4];\n"
                    : "=r"(a[mi][0]), "=r"(a[mi][1]), "=r"(a[mi][2]), "=r"(a[mi][3]) : "r"(addr));
            }
            #pragma unroll
            for (int np = 0; np < 2; np++) {
                uint32_t addr = (uint32_t)__cvta_generic_to_shared(
                    &Bs[st][k16 + (l & 15)][warpN + np * 16 + (l >> 4) * 8]);
                asm volatile("ldmatrix.sync.aligned.m8n8.x4.trans.shared.b16 {%0,%1,%2,%3}, [%4];\n"
                    : "=r"(bfr[np][0]), "=r"(bfr[np][1]), "=r"(bfr[np][2]), "=r"(bfr[np][3]) : "r"(addr));
            }
            #pragma unroll
            for (int mi = 0; mi < 4; mi++)
                #pragma unroll
                for (int nj = 0; nj < 4; nj++) {
                    uint32_t b0 = bfr[nj >> 1][(nj & 1) * 2];
                    uint32_t b1 = bfr[nj >> 1][(nj & 1) * 2 + 1];
                    asm volatile(
                        "mma.sync.aligned.m16n8k16.row.col.f32.bf16.bf16.f32 "
                        "{%0,%1,%2,%3}, {%4,%5,%6,%7}, {%8,%9}, {%0,%1,%2,%3};\n"
                        : "+f"(acc[mi][nj][0]), "+f"(acc[mi][nj][1]),
                          "+f"(acc[mi][nj][2]), "+f"(acc[mi][nj][3])
                        : "r"(a[mi][0]), "r"(a[mi][1]), "r"(a[mi][2]), "r"(a[mi][3]),
                          "r"(b0), "r"(b1));
                }
        }
        __syncthreads();
    }

    #pragma unroll
    for (int mi = 0; mi < 4; mi++) {
        const int r = row0 + warpM + mi * 16 + (l >> 2);
        #pragma unroll
        for (int nj = 0; nj < 4; nj++) {
            const int c = col0 + warpN + nj * 8 + ((l & 3) << 1);
            const float b0 = bias[c], b1 = bias[c + 1];
            float v0 = acc[mi][nj][0] + b0;
            float v1 = acc[mi][nj][1] + b1;
            float v2 = acc[mi][nj][2] + b0;
            float v3 = acc[mi][nj][3] + b1;
            const size_t o0 = (size_t)r * N + c;
            const size_t o1 = (size_t)(r + 8) * N + c;
            if (MODE == 1) {
                __nv_bfloat16* Cm = (__nv_bfloat16*)Cout + (size_t)blockIdx.z * ROWS_ * N;
                *(__nv_bfloat162*)&Cm[o0] = __nv_bfloat162(__float2bfloat16(v0), __float2bfloat16(v1));
                *(__nv_bfloat162*)&Cm[o1] = __nv_bfloat162(__float2bfloat16(v2), __float2bfloat16(v3));
            } else {
                float* Cm = (float*)Cout;
                float2 r0 = *(const float2*)&residual[o0];
                float2 r1 = *(const float2*)&residual[o1];
                *(float2*)&Cm[o0] = make_float2(r0.x + v0, r0.y + v1);
                *(float2*)&Cm[o1] = make_float2(r1.x + v2, r1.y + v3);
            }
        }
    }
}

// ---------------- batched sampler: bf16x2, 32 threads per (m,bq,h) -----------
__global__ void sample_kernel(const __nv_bfloat16* __restrict__ valueAll, // [M][B*Lq][C]
                              const float* __restrict__ ref,
                              const float* __restrict__ offaw,            // (B*Lq, 288)
                              __nv_bfloat16* __restrict__ attn,           // (B*Lq, 1536)
                              const int* __restrict__ shapes_raw,
                              const int* __restrict__ lstart_raw)
{
    const int idx = blockIdx.x * 8 + (threadIdx.x >> 5);   // over M*B*Lq*H
    const int l   = threadIdx.x & 31;                      // channel pair
    if (idx >= M_ * ROWS_ * H_) return;
    const int m   = idx / (ROWS_ * H_);
    const int rem = idx % (ROWS_ * H_);
    const int h   = rem % H_;
    const int bq  = rem / H_;
    const int b   = bq / LQ_;

    const int gh = shapes_raw[0];
    const int w1 = shapes_raw[1];
    const int gw = (w1 != 0) ? w1 : shapes_raw[2];
    const int st = lstart_raw[0];

    const float* fo = offaw + (size_t)bq * FUSEN_ + m * 72;

    float a4[P_];
    float amax = -1e30f;
    #pragma unroll
    for (int p = 0; p < P_; p++) {
        a4[p] = fo[OFFN_ + h * P_ + p];
        amax = fmaxf(amax, a4[p]);
    }
    float asum = 0.f;
    #pragma unroll
    for (int p = 0; p < P_; p++) { a4[p] = __expf(a4[p] - amax); asum += a4[p]; }
    const float ainv = 1.f / asum;

    const float rx = ref[(size_t)bq * 2 + 0];
    const float ry = ref[(size_t)bq * 2 + 1];
    const float inv_w = 1.f / (float)gw;
    const float inv_h = 1.f / (float)gh;

    const __nv_bfloat162* v2 = (const __nv_bfloat162*)
        (valueAll + (size_t)m * ROWS_ * C_);

    float ox_ = 0.f, oy_ = 0.f;
    float2 out = make_float2(0.f, 0.f);
    #pragma unroll
    for (int p = 0; p < P_; p++) {
        const float ox = fo[h * (P_ * 2) + p * 2 + 0];
        const float oy = fo[h * (P_ * 2) + p * 2 + 1];
        const float x = (rx + ox * inv_w) * (float)gw - 0.5f;
        const float y = (ry + oy * inv_h) * (float)gh - 0.5f;
        const float xf = floorf(x);
        const float yf = floorf(y);
        const int x0 = (int)xf;
        const int y0 = (int)yf;
        const float wx = x - xf;
        const float wy = y - yf;
        const float aws = a4[p] * ainv;

        #pragma unroll
        for (int cy = 0; cy < 2; cy++) {
            const int yi = y0 + cy;
            if (yi < 0 || yi >= gh) continue;
            const float wyc = (cy ? wy : (1.f - wy)) * aws;
            #pragma unroll
            for (int cx = 0; cx < 2; cx++) {
                const int xi = x0 + cx;
                if (xi < 0 || xi >= gw) continue;
                const float wgt = wyc * (cx ? wx : (1.f - wx));
                const int pos = st + yi * gw + xi;
                __nv_bfloat162 vv = v2[(((size_t)b * LQ_ + pos) * H_ + h) * 32 + l];
                out.x = fmaf(wgt, __bfloat162float(vv.x), out.x);
                out.y = fmaf(wgt, __bfloat162float(vv.y), out.y);
            }
        }
    }
    __nv_bfloat162* dst = (__nv_bfloat162*)(attn + (size_t)bq * KOUT_ + m * C_ + h * DH_);
    dst[l] = __nv_bfloat162(__float2bfloat16(out.x), __float2bfloat16(out.y));
    (void)ox_; (void)oy_;
}

// ---------------- driver -----------------------------------------------------
extern "C" void kernel_launch(void* const* d_in, const int* in_sizes, int n_in,
                              void* d_out, int out_size)
{
    const float* query = (const float*)d_in[0];
    const float* ref   = (const float*)d_in[1];
    const float* feat  = (const float*)d_in[2];
    const float* feato = (const float*)d_in[3];
    const float* qn_g  = (const float*)d_in[4];
    const float* qn_b  = (const float*)d_in[5];
    const float* fn_g  = (const float*)d_in[6];
    const float* fn_b  = (const float*)d_in[7];
    const float* Wv    = (const float*)d_in[8];
    const float* bv    = (const float*)d_in[9];
    const float* Woff  = (const float*)d_in[10];
    const float* boff  = (const float*)d_in[11];
    const float* Waw   = (const float*)d_in[12];
    const float* baw   = (const float*)d_in[13];
    const float* Wout  = (const float*)d_in[14];
    const float* bout  = (const float*)d_in[15];
    const float* gamma = (const float*)d_in[16];
    const int* shapes  = (const int*)d_in[17];
    const int* lstart  = (const int*)d_in[18];
    float* out = (float*)d_out;

    __nv_bfloat16 *qn, *fn, *value, *attn, *Wv_b, *Wfo_b, *Wout_b;
    float *offaw, *bfo, *bout_t;
    cudaGetSymbolAddress((void**)&qn,     g_qn);
    cudaGetSymbolAddress((void**)&fn,     g_fn);
    cudaGetSymbolAddress((void**)&value,  g_value);
    cudaGetSymbolAddress((void**)&offaw,  g_offaw);
    cudaGetSymbolAddress((void**)&attn,   g_attn);
    cudaGetSymbolAddress((void**)&Wv_b,   g_Wv_b);
    cudaGetSymbolAddress((void**)&Wfo_b,  g_Wfo_b);
    cudaGetSymbolAddress((void**)&bfo,    g_bfo);
    cudaGetSymbolAddress((void**)&Wout_b, g_Wout_b);
    cudaGetSymbolAddress((void**)&bout_t, g_bout);

    // single fused pack
    pack_all_kernel<<<(PACK_TOTAL_ + 255) / 256, 256>>>(
        Wv, Woff, Waw, Wout, gamma, boff, baw, bout,
        Wv_b, Wfo_b, Wout_b, bfo, bout_t);

    // fused warp-per-row LN (5 sources)
    ln_kernel<<<5 * ROWS_ / 8, 256>>>(query, feat, feato, qn_g, qn_b, fn_g, fn_b, qn, fn);

    // off+aw GEMM (N=288)
    gemm64<<<dim3((FUSEN_ + 63) / 64, ROWS_ / 128), 256>>>(qn, Wfo_b, bfo, offaw, FUSEN_);

    // batched value GEMMs: 128x128 tiles, z = modality
    gemm128<C_, 1><<<dim3(C_ / 128, ROWS_ / 128, M_), 256>>>(fn, Wv_b, bv, value, nullptr);

    // batched deformable sampling
    sample_kernel<<<(M_ * ROWS_ * H_) / 8, 256>>>(value, ref, offaw, attn, shapes, lstart);

    // final fused GEMM: out = query + attnAll @ Wout' + bout'
    gemm128<KOUT_, 2><<<dim3(C_ / 128, ROWS_ / 128), 256>>>(attn, Wout_b, bout_t, out, query);
}

// round 7
// speedup vs baseline: 9.6976x; 1.4216x over previous
#include <cuda_runtime.h>
#include <cuda_bf16.h>
#include <cstdint>

#define B_   2
#define LQ_  4096
#define C_   384
#define M_   4
#define H_   6
#define P_   4
#define DH_  64
#define ROWS_ (B_ * LQ_)          // 8192
#define OFFN_ 48
#define AWN_  24
#define FUSEN_ (M_ * (OFFN_ + AWN_))   // 288
#define KOUT_ (M_ * C_)                // 1536

// ---------------- scratch ----------------------------------------------------
__device__ __nv_bfloat16 g_qn    [ROWS_ * C_];
__device__ __nv_bfloat16 g_fn    [M_ * ROWS_ * C_];
__device__ __nv_bfloat16 g_value [M_ * ROWS_ * C_];
__device__ float         g_offaw [ROWS_ * FUSEN_];
__device__ __nv_bfloat16 g_attn  [ROWS_ * KOUT_];
__device__ __nv_bfloat16 g_Wv_b  [M_ * C_ * C_];
__device__ __nv_bfloat16 g_Wfo_b [C_ * FUSEN_];
__device__ float         g_bfo   [FUSEN_];
__device__ __nv_bfloat16 g_Wout_b[KOUT_ * C_];
__device__ float         g_bout  [C_];

// ---------------- fused weight packing (single launch) -----------------------
#define S1_ (M_ * C_ * C_)
#define S2_ (C_ * FUSEN_)
#define S3_ (M_ * C_ * C_)
__global__ void pack_all_kernel(const float* __restrict__ Wv,
                                const float* __restrict__ Woff,
                                const float* __restrict__ Waw,
                                const float* __restrict__ Wout,
                                const float* __restrict__ gamma,
                                const float* __restrict__ boff,
                                const float* __restrict__ baw,
                                const float* __restrict__ bout,
                                __nv_bfloat16* __restrict__ Wv_b,
                                __nv_bfloat16* __restrict__ Wfo_b,
                                __nv_bfloat16* __restrict__ Wout_b,
                                float* __restrict__ bfo,
                                float* __restrict__ bout_t)
{
    int i = blockIdx.x * blockDim.x + threadIdx.x;
    if (i < S1_) {
        Wv_b[i] = __float2bfloat16(Wv[i]);
    } else if (i < S1_ + S2_) {
        int j = i - S1_;
        int k = j / FUSEN_, jj = j % FUSEN_;
        int m = jj / 72, r = jj % 72;
        float v = (r < OFFN_) ? Woff[((size_t)m * C_ + k) * OFFN_ + r]
                              : Waw [((size_t)m * C_ + k) * AWN_  + (r - OFFN_)];
        Wfo_b[j] = __float2bfloat16(v);
    } else if (i < S1_ + S2_ + S3_) {
        int j = i - S1_ - S2_;
        int m = j / (C_ * C_);
        int c = j % C_;
        Wout_b[j] = __float2bfloat16(gamma[m * C_ + c] * Wout[j]);
    } else {
        int j = i - S1_ - S2_ - S3_;
        if (j < FUSEN_) {
            int m = j / 72, r = j % 72;
            bfo[j] = (r < OFFN_) ? boff[m * OFFN_ + r] : baw[m * AWN_ + r - OFFN_];
        } else if (j < FUSEN_ + C_) {
            int c = j - FUSEN_;
            float s = 0.f;
            #pragma unroll
            for (int m = 0; m < M_; m++) s += gamma[m * C_ + c] * bout[m * C_ + c];
            bout_t[c] = s;
        }
    }
}
#define PACK_TOTAL_ (S1_ + S2_ + S3_ + FUSEN_ + C_)

// ---------------- warp-per-row LayerNorm (5 sources fused) -------------------
__global__ void ln_kernel(const float* __restrict__ query,
                          const float* __restrict__ feat,
                          const float* __restrict__ feato,
                          const float* __restrict__ qn_g, const float* __restrict__ qn_b,
                          const float* __restrict__ fn_g, const float* __restrict__ fn_b,
                          __nv_bfloat16* __restrict__ qn,
                          __nv_bfloat16* __restrict__ fnAll)
{
    const int grow = blockIdx.x * 8 + (threadIdx.x >> 5);
    const int l = threadIdx.x & 31;
    const int src = grow / ROWS_;
    const int row = grow - src * ROWS_;

    const float* xbase = (src == 0) ? query : (src == 1 ? feat
                         : feato + (size_t)(src - 2) * ROWS_ * C_);
    const float* g = (src == 0) ? qn_g : fn_g + (src - 1) * C_;
    const float* b = (src == 0) ? qn_b : fn_b + (src - 1) * C_;
    __nv_bfloat16* y = (src == 0) ? qn + (size_t)row * C_
                                  : fnAll + ((size_t)(src - 1) * ROWS_ + row) * C_;
    const float4* xr = (const float4*)(xbase + (size_t)row * C_);

    float4 v[3];
    float sum = 0.f, sumsq = 0.f;
    #pragma unroll
    for (int k = 0; k < 3; k++) {
        v[k] = xr[l + 32 * k];
        sum   += v[k].x + v[k].y + v[k].z + v[k].w;
        sumsq += v[k].x * v[k].x + v[k].y * v[k].y + v[k].z * v[k].z + v[k].w * v[k].w;
    }
    #pragma unroll
    for (int o = 16; o; o >>= 1) {
        sum   += __shfl_xor_sync(0xffffffffu, sum, o);
        sumsq += __shfl_xor_sync(0xffffffffu, sumsq, o);
    }
    const float mean = sum * (1.f / C_);
    const float var  = sumsq * (1.f / C_) - mean * mean;
    const float inv  = rsqrtf(var + 1e-6f);

    const float4* g4 = (const float4*)g;
    const float4* b4 = (const float4*)b;
    #pragma unroll
    for (int k = 0; k < 3; k++) {
        float4 gg = g4[l + 32 * k];
        float4 bb = b4[l + 32 * k];
        __nv_bfloat16 o0 = __float2bfloat16((v[k].x - mean) * inv * gg.x + bb.x);
        __nv_bfloat16 o1 = __float2bfloat16((v[k].y - mean) * inv * gg.y + bb.y);
        __nv_bfloat16 o2 = __float2bfloat16((v[k].z - mean) * inv * gg.z + bb.z);
        __nv_bfloat16 o3 = __float2bfloat16((v[k].w - mean) * inv * gg.w + bb.w);
        uint2 pk;
        pk.x = ((uint32_t)__bfloat16_as_ushort(o1) << 16) | __bfloat16_as_ushort(o0);
        pk.y = ((uint32_t)__bfloat16_as_ushort(o3) << 16) | __bfloat16_as_ushort(o2);
        *(uint2*)&y[(l + 32 * k) * 4] = pk;
    }
}

// ---------------- 64-wide GEMM (offaw only, N=288, fp32 out) -----------------
#define AS_STRIDE 40
#define BS_STRIDE 72
__global__ __launch_bounds__(256) void gemm64(const __nv_bfloat16* __restrict__ A,
                                              const __nv_bfloat16* __restrict__ W,
                                              const float* __restrict__ bias,
                                              float* __restrict__ Cm, int N)
{
    __shared__ alignas(16) __nv_bfloat16 As[2][128][AS_STRIDE];
    __shared__ alignas(16) __nv_bfloat16 Bs[2][32][BS_STRIDE];
    const int tid = threadIdx.x;
    const int w = tid >> 5, l = tid & 31;
    const int warpM = (w & 3) << 5;
    const int warpN = (w >> 2) << 5;
    const int row0 = blockIdx.y * 128;
    const int col0 = blockIdx.x * 64;

    float acc[2][4][4];
    #pragma unroll
    for (int mi = 0; mi < 2; mi++)
        #pragma unroll
        for (int nj = 0; nj < 4; nj++)
            #pragma unroll
            for (int q = 0; q < 4; q++) acc[mi][nj][q] = 0.f;

    const int br = tid >> 3, bch = tid & 7;
    const int KIT = C_ / 32;

    for (int it = 0; it <= KIT; it++) {
        if (it < KIT) {
            const int st = it & 1;
            const int k0 = it * 32;
            #pragma unroll
            for (int i = 0; i < 2; i++) {
                int q = tid * 2 + i;
                int r = q >> 2, kc = q & 3;
                uint32_t d = (uint32_t)__cvta_generic_to_shared(&As[st][r][kc * 8]);
                const __nv_bfloat16* s = A + (size_t)(row0 + r) * C_ + k0 + kc * 8;
                asm volatile("cp.async.cg.shared.global [%0], [%1], 16;\n" :: "r"(d), "l"(s));
            }
            {
                int c = bch * 8;
                uint32_t d = (uint32_t)__cvta_generic_to_shared(&Bs[st][br][c]);
                const __nv_bfloat16* s = W + (size_t)(k0 + br) * N + col0 + c;
                int sb = (col0 + c < N) ? 16 : 0;
                if (sb == 0) s = W;
                asm volatile("cp.async.cg.shared.global [%0], [%1], 16, %2;\n"
                             :: "r"(d), "l"(s), "r"(sb));
            }
            asm volatile("cp.async.commit_group;\n");
        }
        if (it == 0) continue;
        if (it < KIT) asm volatile("cp.async.wait_group 1;\n");
        else          asm volatile("cp.async.wait_group 0;\n");
        __syncthreads();

        const int st = (it - 1) & 1;
        #pragma unroll
        for (int s = 0; s < 2; s++) {
            const int k16 = s * 16;
            uint32_t a[2][4], bfr[2][4];
            #pragma unroll
            for (int mi = 0; mi < 2; mi++) {
                uint32_t addr = (uint32_t)__cvta_generic_to_shared(
                    &As[st][warpM + mi * 16 + (l & 15)][k16 + (l >> 4) * 8]);
                asm volatile("ldmatrix.sync.aligned.m8n8.x4.shared.b16 {%0,%1,%2,%3}, [%4];\n"
                    : "=r"(a[mi][0]), "=r"(a[mi][1]), "=r"(a[mi][2]), "=r"(a[mi][3]) : "r"(addr));
            }
            #pragma unroll
            for (int np = 0; np < 2; np++) {
                uint32_t addr = (uint32_t)__cvta_generic_to_shared(
                    &Bs[st][k16 + (l & 15)][warpN + np * 16 + (l >> 4) * 8]);
                asm volatile("ldmatrix.sync.aligned.m8n8.x4.trans.shared.b16 {%0,%1,%2,%3}, [%4];\n"
                    : "=r"(bfr[np][0]), "=r"(bfr[np][1]), "=r"(bfr[np][2]), "=r"(bfr[np][3]) : "r"(addr));
            }
            #pragma unroll
            for (int mi = 0; mi < 2; mi++)
                #pragma unroll
                for (int nj = 0; nj < 4; nj++) {
                    uint32_t b0 = bfr[nj >> 1][(nj & 1) * 2];
                    uint32_t b1 = bfr[nj >> 1][(nj & 1) * 2 + 1];
                    asm volatile(
                        "mma.sync.aligned.m16n8k16.row.col.f32.bf16.bf16.f32 "
                        "{%0,%1,%2,%3}, {%4,%5,%6,%7}, {%8,%9}, {%0,%1,%2,%3};\n"
                        : "+f"(acc[mi][nj][0]), "+f"(acc[mi][nj][1]),
                          "+f"(acc[mi][nj][2]), "+f"(acc[mi][nj][3])
                        : "r"(a[mi][0]), "r"(a[mi][1]), "r"(a[mi][2]), "r"(a[mi][3]),
                          "r"(b0), "r"(b1));
                }
        }
        __syncthreads();
    }

    #pragma unroll
    for (int mi = 0; mi < 2; mi++) {
        const int r = row0 + warpM + mi * 16 + (l >> 2);
        #pragma unroll
        for (int nj = 0; nj < 4; nj++) {
            const int c = col0 + warpN + nj * 8 + ((l & 3) << 1);
            if (c >= N) continue;
            const float b0 = bias[c], b1 = bias[c + 1];
            *(float2*)&Cm[(size_t)r * N + c]       = make_float2(acc[mi][nj][0] + b0, acc[mi][nj][1] + b1);
            *(float2*)&Cm[(size_t)(r + 8) * N + c] = make_float2(acc[mi][nj][2] + b0, acc[mi][nj][3] + b1);
        }
    }
}

// ---------------- 128x128 GEMM, N=384 exact, 2-stage static smem -------------
#define BS2_STRIDE 136
template<int KA, int MODE>
__global__ __launch_bounds__(256) void gemm128(const __nv_bfloat16* __restrict__ A,
                                               const __nv_bfloat16* __restrict__ W,
                                               const float* __restrict__ bias,
                                               void* __restrict__ Cout,
                                               const float* __restrict__ residual)
{
    __shared__ alignas(16) __nv_bfloat16 As[2][128][AS_STRIDE];
    __shared__ alignas(16) __nv_bfloat16 Bs[2][32][BS2_STRIDE];
    const int N = C_;
    const int tid = threadIdx.x;
    const int w = tid >> 5, l = tid & 31;
    const int warpM = (w & 1) << 6;     // 0,64
    const int warpN = (w >> 1) << 5;    // 0,32,64,96
    const int row0 = blockIdx.y * 128;
    const int col0 = blockIdx.x * 128;

    if (MODE == 1) {
        const int zb = blockIdx.z;
        A    += (size_t)zb * ROWS_ * KA;
        W    += (size_t)zb * KA * N;
        bias += (size_t)zb * N;
    }

    float acc[4][4][4];
    #pragma unroll
    for (int mi = 0; mi < 4; mi++)
        #pragma unroll
        for (int nj = 0; nj < 4; nj++)
            #pragma unroll
            for (int q = 0; q < 4; q++) acc[mi][nj][q] = 0.f;

    const int KIT = KA / 32;

    for (int it = 0; it <= KIT; it++) {
        if (it < KIT) {
            const int st = it & 1;
            const int k0 = it * 32;
            #pragma unroll
            for (int i = 0; i < 2; i++) {
                int q = tid * 2 + i;
                int r = q >> 2, kc = q & 3;
                uint32_t d = (uint32_t)__cvta_generic_to_shared(&As[st][r][kc * 8]);
                const __nv_bfloat16* s = A + (size_t)(row0 + r) * KA + k0 + kc * 8;
                asm volatile("cp.async.cg.shared.global [%0], [%1], 16;\n" :: "r"(d), "l"(s));
            }
            #pragma unroll
            for (int i = 0; i < 2; i++) {
                int r = (tid >> 4) + i * 16;
                int c = (tid & 15) * 8;
                uint32_t d = (uint32_t)__cvta_generic_to_shared(&Bs[st][r][c]);
                const __nv_bfloat16* s = W + (size_t)(k0 + r) * N + col0 + c;
                asm volatile("cp.async.cg.shared.global [%0], [%1], 16;\n" :: "r"(d), "l"(s));
            }
            asm volatile("cp.async.commit_group;\n");
        }
        if (it == 0) continue;
        if (it < KIT) asm volatile("cp.async.wait_group 1;\n");
        else          asm volatile("cp.async.wait_group 0;\n");
        __syncthreads();

        const int st = (it - 1) & 1;
        #pragma unroll
        for (int s = 0; s < 2; s++) {
            const int k16 = s * 16;
            uint32_t a[4][4], bfr[2][4];
            #pragma unroll
            for (int mi = 0; mi < 4; mi++) {
                uint32_t addr = (uint32_t)__cvta_generic_to_shared(
                    &As[st][warpM + mi * 16 + (l & 15)][k16 + (l >> 4) * 8]);
                asm volatile("ldmatrix.sync.aligned.m8n8.x4.shared.b16 {%0,%1,%2,%3}, [%4];\n"
                    : "=r"(a[mi][0]), "=r"(a[mi][1]), "=r"(a[mi][2]), "=r"(a[mi][3]) : "r"(addr));
            }
            #pragma unroll
            for (int np = 0; np < 2; np++) {
                uint32_t addr = (uint32_t)__cvta_generic_to_shared(
                    &Bs[st][k16 + (l & 15)][warpN + np * 16 + (l >> 4) * 8]);
                asm volatile("ldmatrix.sync.aligned.m8n8.x4.trans.shared.b16 {%0,%1,%2,%3}, [%4];\n"
                    : "=r"(bfr[np][0]), "=r"(bfr[np][1]), "=r"(bfr[np][2]), "=r"(bfr[np][3]) : "r"(addr));
            }
            #pragma unroll
            for (int mi = 0; mi < 4; mi++)
                #pragma unroll
                for (int nj = 0; nj < 4; nj++) {
                    uint32_t b0 = bfr[nj >> 1][(nj & 1) * 2];
                    uint32_t b1 = bfr[nj >> 1][(nj & 1) * 2 + 1];
                    asm volatile(
                        "mma.sync.aligned.m16n8k16.row.col.f32.bf16.bf16.f32 "
                        "{%0,%1,%2,%3}, {%4,%5,%6,%7}, {%8,%9}, {%0,%1,%2,%3};\n"
                        : "+f"(acc[mi][nj][0]), "+f"(acc[mi][nj][1]),
                          "+f"(acc[mi][nj][2]), "+f"(acc[mi][nj][3])
                        : "r"(a[mi][0]), "r"(a[mi][1]), "r"(a[mi][2]), "r"(a[mi][3]),
                          "r"(b0), "r"(b1));
                }
        }
        __syncthreads();
    }

    #pragma unroll
    for (int mi = 0; mi < 4; mi++) {
        const int r = row0 + warpM + mi * 16 + (l >> 2);
        #pragma unroll
        for (int nj = 0; nj < 4; nj++) {
            const int c = col0 + warpN + nj * 8 + ((l & 3) << 1);
            const float b0 = bias[c], b1 = bias[c + 1];
            float v0 = acc[mi][nj][0] + b0;
            float v1 = acc[mi][nj][1] + b1;
            float v2 = acc[mi][nj][2] + b0;
            float v3 = acc[mi][nj][3] + b1;
            const size_t o0 = (size_t)r * N + c;
            const size_t o1 = (size_t)(r + 8) * N + c;
            if (MODE == 1) {
                __nv_bfloat16* Cm = (__nv_bfloat16*)Cout + (size_t)blockIdx.z * ROWS_ * N;
                *(__nv_bfloat162*)&Cm[o0] = __nv_bfloat162(__float2bfloat16(v0), __float2bfloat16(v1));
                *(__nv_bfloat162*)&Cm[o1] = __nv_bfloat162(__float2bfloat16(v2), __float2bfloat16(v3));
            } else {
                float* Cm = (float*)Cout;
                float2 r0 = *(const float2*)&residual[o0];
                float2 r1 = *(const float2*)&residual[o1];
                *(float2*)&Cm[o0] = make_float2(r0.x + v0, r0.y + v1);
                *(float2*)&Cm[o1] = make_float2(r1.x + v2, r1.y + v3);
            }
        }
    }
}

// ---------------- batched sampler: 8 channels/thread via uint4 ---------------
__global__ void sample_kernel(const __nv_bfloat16* __restrict__ valueAll, // [M][B*Lq][C]
                              const float* __restrict__ ref,
                              const float* __restrict__ offaw,            // (B*Lq, 288)
                              __nv_bfloat16* __restrict__ attn,           // (B*Lq, 1536)
                              const int* __restrict__ shapes_raw,
                              const int* __restrict__ lstart_raw)
{
    const int t   = threadIdx.x;
    const int idx = blockIdx.x * 32 + (t >> 3);   // over M*B*Lq*H
    const int l8  = t & 7;                        // 8-channel chunk
    const int m   = idx / (ROWS_ * H_);
    const int rem = idx % (ROWS_ * H_);
    const int h   = rem % H_;
    const int bq  = rem / H_;
    const int b   = bq / LQ_;

    const int gh = shapes_raw[0];
    const int w1 = shapes_raw[1];
    const int gw = (w1 != 0) ? w1 : shapes_raw[2];
    const int st = lstart_raw[0];

    const float* fo = offaw + (size_t)bq * FUSEN_ + m * 72;

    float a4[P_];
    float amax = -1e30f;
    #pragma unroll
    for (int p = 0; p < P_; p++) {
        a4[p] = fo[OFFN_ + h * P_ + p];
        amax = fmaxf(amax, a4[p]);
    }
    float asum = 0.f;
    #pragma unroll
    for (int p = 0; p < P_; p++) { a4[p] = __expf(a4[p] - amax); asum += a4[p]; }
    const float ainv = 1.f / asum;

    const float rx = ref[(size_t)bq * 2 + 0];
    const float ry = ref[(size_t)bq * 2 + 1];
    const float inv_w = 1.f / (float)gw;
    const float inv_h = 1.f / (float)gh;

    // uint4 view: 8 bf16 per element; index = ((b*LQ+pos)*H + h)*8 + l8
    const uint4* vb = (const uint4*)(valueAll + (size_t)m * ROWS_ * C_);
    const size_t hbase = ((size_t)b * LQ_) * H_ + h;

    float out[8] = {};
    #pragma unroll
    for (int p = 0; p < P_; p++) {
        const float ox = fo[h * (P_ * 2) + p * 2 + 0];
        const float oy = fo[h * (P_ * 2) + p * 2 + 1];
        const float x = (rx + ox * inv_w) * (float)gw - 0.5f;
        const float y = (ry + oy * inv_h) * (float)gh - 0.5f;
        const float xf = floorf(x);
        const float yf = floorf(y);
        const int x0 = (int)xf;
        const int y0 = (int)yf;
        const float wx = x - xf;
        const float wy = y - yf;
        const float aws = a4[p] * ainv;

        #pragma unroll
        for (int cy = 0; cy < 2; cy++) {
            const int yi = y0 + cy;
            if (yi < 0 || yi >= gh) continue;
            const float wyc = (cy ? wy : (1.f - wy)) * aws;
            #pragma unroll
            for (int cx = 0; cx < 2; cx++) {
                const int xi = x0 + cx;
                if (xi < 0 || xi >= gw) continue;
                const float wgt = wyc * (cx ? wx : (1.f - wx));
                const int pos = st + yi * gw + xi;
                uint4 v = vb[(hbase + (size_t)pos * H_) * 8 + l8];
                const uint32_t* vw = (const uint32_t*)&v;
                #pragma unroll
                for (int k = 0; k < 4; k++) {
                    __nv_bfloat162 pr = *(const __nv_bfloat162*)&vw[k];
                    out[2 * k]     = fmaf(wgt, __bfloat162float(pr.x), out[2 * k]);
                    out[2 * k + 1] = fmaf(wgt, __bfloat162float(pr.y), out[2 * k + 1]);
                }
            }
        }
    }
    uint4 pk;
    uint32_t* pw = (uint32_t*)&pk;
    #pragma unroll
    for (int k = 0; k < 4; k++) {
        __nv_bfloat162 pr(__float2bfloat16(out[2 * k]), __float2bfloat16(out[2 * k + 1]));
        pw[k] = *(const uint32_t*)&pr;
    }
    *(uint4*)(attn + (size_t)bq * KOUT_ + m * C_ + h * DH_ + l8 * 8) = pk;
}

// ---------------- driver -----------------------------------------------------
extern "C" void kernel_launch(void* const* d_in, const int* in_sizes, int n_in,
                              void* d_out, int out_size)
{
    const float* query = (const float*)d_in[0];
    const float* ref   = (const float*)d_in[1];
    const float* feat  = (const float*)d_in[2];
    const float* feato = (const float*)d_in[3];
    const float* qn_g  = (const float*)d_in[4];
    const float* qn_b  = (const float*)d_in[5];
    const float* fn_g  = (const float*)d_in[6];
    const float* fn_b  = (const float*)d_in[7];
    const float* Wv    = (const float*)d_in[8];
    const float* bv    = (const float*)d_in[9];
    const float* Woff  = (const float*)d_in[10];
    const float* boff  = (const float*)d_in[11];
    const float* Waw   = (const float*)d_in[12];
    const float* baw   = (const float*)d_in[13];
    const float* Wout  = (const float*)d_in[14];
    const float* bout  = (const float*)d_in[15];
    const float* gamma = (const float*)d_in[16];
    const int* shapes  = (const int*)d_in[17];
    const int* lstart  = (const int*)d_in[18];
    float* out = (float*)d_out;

    __nv_bfloat16 *qn, *fn, *value, *attn, *Wv_b, *Wfo_b, *Wout_b;
    float *offaw, *bfo, *bout_t;
    cudaGetSymbolAddress((void**)&qn,     g_qn);
    cudaGetSymbolAddress((void**)&fn,     g_fn);
    cudaGetSymbolAddress((void**)&value,  g_value);
    cudaGetSymbolAddress((void**)&offaw,  g_offaw);
    cudaGetSymbolAddress((void**)&attn,   g_attn);
    cudaGetSymbolAddress((void**)&Wv_b,   g_Wv_b);
    cudaGetSymbolAddress((void**)&Wfo_b,  g_Wfo_b);
    cudaGetSymbolAddress((void**)&bfo,    g_bfo);
    cudaGetSymbolAddress((void**)&Wout_b, g_Wout_b);
    cudaGetSymbolAddress((void**)&bout_t, g_bout);

    pack_all_kernel<<<(PACK_TOTAL_ + 255) / 256, 256>>>(
        Wv, Woff, Waw, Wout, gamma, boff, baw, bout,
        Wv_b, Wfo_b, Wout_b, bfo, bout_t);

    ln_kernel<<<5 * ROWS_ / 8, 256>>>(query, feat, feato, qn_g, qn_b, fn_g, fn_b, qn, fn);

    gemm64<<<dim3((FUSEN_ + 63) / 64, ROWS_ / 128), 256>>>(qn, Wfo_b, bfo, offaw, FUSEN_);

    gemm128<C_, 1><<<dim3(C_ / 128, ROWS_ / 128, M_), 256>>>(fn, Wv_b, bv, value, nullptr);

    sample_kernel<<<(M_ * ROWS_ * H_) / 32, 256>>>(value, ref, offaw, attn, shapes, lstart);

    gemm128<KOUT_, 2><<<dim3(C_ / 128, ROWS_ / 128), 256>>>(attn, Wout_b, bout_t, out, query);
}